// round 1
// baseline (speedup 1.0000x reference)
#include <cuda_runtime.h>
#include <math.h>

#define Bx 128
#define Nx 1023
#define Hx 256
#define Xx 256
#define Cx 10
#define NLEAF 512
#define GH3 768      // 3*H
#define NC 1280      // 2H (f gates) + 3H (iou)
#define K2H 512      // 2*H

// ---- device-global scratch (no allocations allowed) ----
__device__ float g_h[(size_t)Bx * Nx * Hx];          // 134 MB
__device__ float g_c[(size_t)Bx * Nx * Hx];          // 134 MB
__device__ float g_scr[(size_t)Bx * NLEAF * GH3];    // 201 MB (reused per level)
__device__ float g_Wc[NC * K2H];                     // packed [Uf_W ; U_iou]
__device__ float g_q[Bx * Hx];
__device__ float g_ctx[Bx * Hx];

__device__ __forceinline__ float sigm(float x) { return 1.f / (1.f + expf(-x)); }

// ---- pack [Uf_W (512x512) ; U_iou (768x512)] into one 1280x512 matrix ----
__global__ void pack_wc_k(const float* __restrict__ Uf_W,
                          const float* __restrict__ U_iou) {
    int i = blockIdx.x * 256 + threadIdx.x;
    if (i >= NC * K2H) return;
    g_Wc[i] = (i < K2H * K2H) ? Uf_W[i] : U_iou[i - K2H * K2H];
}

// ---- classic 128x128x16 SGEMM, 256 threads, 8x8 per-thread ----
// out[r][n] = sum_k A[r][k] * Wt[n][k]   (both K-major)
// MODE 0: A row r=(b*512+l) -> emb[wordid[b, 511+l]]   (K=256, N=768, Wt=W_iou)
// MODE 1: A row r=(b*npar+pl) -> g_h[b, 2*(ps+pl)+1, :] (512 contiguous, K=512, N=1280, Wt=g_Wc)
template <int MODE>
__global__ __launch_bounds__(256) void sgemm_k(
    const float* __restrict__ WtIn, int Ncols, int K,
    const int* __restrict__ wordid, const float* __restrict__ emb,
    int ps, int shift) {
    __shared__ float As[16][128];
    __shared__ float Bs[16][128];
    const float* Wt = (MODE == 1) ? (const float*)g_Wc : WtIn;
    int tid = threadIdx.x;
    int rowStart = blockIdx.x * 128, colStart = blockIdx.y * 128;
    int lr = tid >> 2, q4 = (tid & 3) << 2;

    const float* aptr[2];
#pragma unroll
    for (int hh = 0; hh < 2; hh++) {
        int r = rowStart + lr + hh * 64;
        if (MODE == 0) {
            int b = r >> 9, l = r & 511;
            int w = wordid[b * Nx + (NLEAF - 1) + l];
            aptr[hh] = emb + (size_t)w * Xx;
        } else {
            int b = r >> shift, pl = r & ((1 << shift) - 1);
            int child1 = 2 * (ps + pl) + 1;
            aptr[hh] = g_h + ((size_t)(b * Nx + child1)) * Hx;
        }
    }
    const float* bptr[2];
    bptr[0] = Wt + (size_t)(colStart + lr) * K;
    bptr[1] = bptr[0] + (size_t)64 * K;

    int ty = tid >> 4, tx = tid & 15;
    float acc[8][8];
#pragma unroll
    for (int i = 0; i < 8; i++)
#pragma unroll
        for (int j = 0; j < 8; j++) acc[i][j] = 0.f;

    for (int k0 = 0; k0 < K; k0 += 16) {
#pragma unroll
        for (int hh = 0; hh < 2; hh++) {
            float4 va = *(const float4*)(aptr[hh] + k0 + q4);
            As[q4 + 0][lr + hh * 64] = va.x;
            As[q4 + 1][lr + hh * 64] = va.y;
            As[q4 + 2][lr + hh * 64] = va.z;
            As[q4 + 3][lr + hh * 64] = va.w;
            float4 vb = *(const float4*)(bptr[hh] + k0 + q4);
            Bs[q4 + 0][lr + hh * 64] = vb.x;
            Bs[q4 + 1][lr + hh * 64] = vb.y;
            Bs[q4 + 2][lr + hh * 64] = vb.z;
            Bs[q4 + 3][lr + hh * 64] = vb.w;
        }
        __syncthreads();
#pragma unroll
        for (int kk = 0; kk < 16; kk++) {
            float4 a0 = *(const float4*)&As[kk][ty * 8];
            float4 a1 = *(const float4*)&As[kk][ty * 8 + 4];
            float4 b0 = *(const float4*)&Bs[kk][tx * 8];
            float4 b1 = *(const float4*)&Bs[kk][tx * 8 + 4];
            float av[8] = {a0.x, a0.y, a0.z, a0.w, a1.x, a1.y, a1.z, a1.w};
            float bv[8] = {b0.x, b0.y, b0.z, b0.w, b1.x, b1.y, b1.z, b1.w};
#pragma unroll
            for (int i = 0; i < 8; i++)
#pragma unroll
                for (int j = 0; j < 8; j++) acc[i][j] += av[i] * bv[j];
        }
        __syncthreads();
    }
#pragma unroll
    for (int i = 0; i < 8; i++) {
        size_t ro = ((size_t)(rowStart + ty * 8 + i)) * Ncols + colStart + tx * 8;
        *(float4*)(g_scr + ro) = make_float4(acc[i][0], acc[i][1], acc[i][2], acc[i][3]);
        *(float4*)(g_scr + ro + 4) = make_float4(acc[i][4], acc[i][5], acc[i][6], acc[i][7]);
    }
}

// ---- leaf epilogue: iou -> (h, c) at nodes 511..1022 ----
__global__ void leaf_node_k(const float* __restrict__ b_iou,
                            const float* __restrict__ c0) {
    int i = blockIdx.x * 256 + threadIdx.x;
    if (i >= Bx * NLEAF * Hx) return;
    int j = i & 255;
    int rl = i >> 8;              // b*512 + l
    int b = rl >> 9, l = rl & 511;
    const float* row = g_scr + (size_t)rl * GH3;
    float iv = row[j] + b_iou[j];
    float ov = row[256 + j] + b_iou[256 + j];
    float uv = row[512 + j] + b_iou[512 + j];
    size_t idx = ((size_t)(b * Nx + (NLEAF - 1) + l)) * Hx + j;
    float c = sigm(iv) * tanhf(uv) + c0[idx];
    float h = sigm(ov) * tanhf(c);
    g_c[idx] = c;
    g_h[idx] = h;
}

// ---- level epilogue: [f1,f2,iou] + child c -> parent (h, c) ----
__global__ void level_node_k(const float* __restrict__ b_iou,
                             const float* __restrict__ Uf_b, int ps, int shift) {
    int total = (Bx << shift) * Hx;
    int i = blockIdx.x * 256 + threadIdx.x;
    if (i >= total) return;
    int j = i & 255;
    int rl = i >> 8;                       // b*npar + pl
    int b = rl >> shift, pl = rl & ((1 << shift) - 1);
    const float* row = g_scr + (size_t)rl * NC;
    int p = ps + pl;
    size_t ci1 = ((size_t)(b * Nx + 2 * p + 1)) * Hx + j;
    float f1 = sigm(row[j] + Uf_b[j]);
    float f2 = sigm(row[256 + j] + Uf_b[256 + j]);
    float csum = f1 * g_c[ci1] + f2 * g_c[ci1 + Hx];
    float iv = row[512 + j] + b_iou[j];
    float ov = row[768 + j] + b_iou[256 + j];
    float uv = row[1024 + j] + b_iou[512 + j];
    float c = sigm(iv) * tanhf(uv) + csum;
    float h = sigm(ov) * tanhf(c);
    size_t pi = ((size_t)(b * Nx + p)) * Hx + j;
    g_c[pi] = c;
    g_h[pi] = h;
}

// ---- q[b] = Wmem^T @ h[b,0,:]  (scores factored: dec^T Wmem h = q . h) ----
__global__ void q_k(const float* __restrict__ Wmem) {
    int b = blockIdx.x, h = threadIdx.x;
    __shared__ float dec[256];
    dec[h] = g_h[((size_t)(b * Nx)) * Hx + h];
    __syncthreads();
    float s = 0.f;
#pragma unroll 4
    for (int g = 0; g < 256; g++) s += dec[g] * Wmem[g * 256 + h];
    g_q[b * Hx + h] = s;
}

// ---- per-batch fused scores + softmax + context ----
__global__ __launch_bounds__(1024) void attn_k() {
    __shared__ float q[256];
    __shared__ float sc[1024];
    __shared__ float red[32];
    __shared__ float ctxp[4][256];
    __shared__ float stat[2];
    int b = blockIdx.x, tid = threadIdx.x;
    int warp = tid >> 5, lane = tid & 31;
    if (tid < 256) q[tid] = g_q[b * Hx + tid];
    __syncthreads();
    const float* hb = g_h + (size_t)b * Nx * Hx;
    for (int n = warp; n < Nx; n += 32) {
        const float* hr = hb + (size_t)n * Hx;
        float s = 0.f;
#pragma unroll
        for (int kk = 0; kk < 8; kk++) s += q[lane + kk * 32] * hr[lane + kk * 32];
#pragma unroll
        for (int o = 16; o; o >>= 1) s += __shfl_xor_sync(0xffffffffu, s, o);
        if (lane == 0) sc[n] = s;
    }
    __syncthreads();
    float sraw = (tid < Nx) ? sc[tid] : -3.4e38f;
    float v = sraw;
#pragma unroll
    for (int o = 16; o; o >>= 1) v = fmaxf(v, __shfl_xor_sync(0xffffffffu, v, o));
    if (lane == 0) red[warp] = v;
    __syncthreads();
    if (warp == 0) {
        float m = red[lane];
#pragma unroll
        for (int o = 16; o; o >>= 1) m = fmaxf(m, __shfl_xor_sync(0xffffffffu, m, o));
        if (lane == 0) stat[0] = m;
    }
    __syncthreads();
    float m = stat[0];
    float e = (tid < Nx) ? expf(sraw - m) : 0.f;
    sc[tid] = e;  // own-slot overwrite; everyone else done reading others' scores
    float s = e;
#pragma unroll
    for (int o = 16; o; o >>= 1) s += __shfl_xor_sync(0xffffffffu, s, o);
    if (lane == 0) red[warp] = s;
    __syncthreads();
    if (warp == 0) {
        float S = red[lane];
#pragma unroll
        for (int o = 16; o; o >>= 1) S += __shfl_xor_sync(0xffffffffu, S, o);
        if (lane == 0) stat[1] = S;
    }
    __syncthreads();
    float Sinv = 1.f / stat[1];
    int grp = tid >> 8, j = tid & 255;
    float p = 0.f;
    for (int n = grp; n < Nx; n += 4) p += sc[n] * hb[(size_t)n * Hx + j];
    ctxp[grp][j] = p;
    __syncthreads();
    if (tid < 256) {
        g_ctx[b * Hx + tid] =
            (ctxp[0][tid] + ctxp[1][tid] + ctxp[2][tid] + ctxp[3][tid]) * Sinv;
    }
}

// ---- head: hid = relu(ctx @ wh_W^T + wh_b); out = hid @ lin_W^T + lin_b ----
__global__ void final_k(const float* __restrict__ wh_W,
                        const float* __restrict__ wh_b,
                        const float* __restrict__ lin_W,
                        const float* __restrict__ lin_b,
                        float* __restrict__ out) {
    int b = blockIdx.x, tid = threadIdx.x;
    int warp = tid >> 5, lane = tid & 31;
    __shared__ float ctx[256];
    __shared__ float hid[256];
    ctx[tid] = g_ctx[b * Hx + tid];
    __syncthreads();
    for (int h = warp; h < 256; h += 8) {
        const float* wr = wh_W + (size_t)h * 256;
        float s = 0.f;
#pragma unroll
        for (int kk = 0; kk < 8; kk++) s += ctx[lane + kk * 32] * wr[lane + kk * 32];
#pragma unroll
        for (int o = 16; o; o >>= 1) s += __shfl_xor_sync(0xffffffffu, s, o);
        if (lane == 0) hid[h] = fmaxf(s + wh_b[h], 0.f);
    }
    __syncthreads();
    if (warp == 0) {
        for (int cc = 0; cc < Cx; cc++) {
            const float* lr = lin_W + (size_t)cc * 256;
            float s = 0.f;
#pragma unroll
            for (int kk = 0; kk < 8; kk++) s += hid[lane + kk * 32] * lr[lane + kk * 32];
#pragma unroll
            for (int o = 16; o; o >>= 1) s += __shfl_xor_sync(0xffffffffu, s, o);
            if (lane == 0) out[b * Cx + cc] = s + lin_b[cc];
        }
    }
}

extern "C" void kernel_launch(void* const* d_in, const int* in_sizes, int n_in,
                              void* d_out, int out_size) {
    const int* wordid   = (const int*)d_in[0];
    // d_in[1] = h0 (unused: every node is overwritten)
    const float* c0     = (const float*)d_in[2];
    const float* emb    = (const float*)d_in[3];
    const float* W_iou  = (const float*)d_in[4];
    const float* U_iou  = (const float*)d_in[5];
    const float* b_iou  = (const float*)d_in[6];
    const float* Uf_W   = (const float*)d_in[7];
    const float* Uf_b   = (const float*)d_in[8];
    const float* Wmem   = (const float*)d_in[9];
    const float* wh_W   = (const float*)d_in[10];
    const float* wh_b   = (const float*)d_in[11];
    const float* lin_W  = (const float*)d_in[12];
    const float* lin_b  = (const float*)d_in[13];
    float* out = (float*)d_out;
    (void)in_sizes; (void)n_in; (void)out_size;

    pack_wc_k<<<(NC * K2H + 255) / 256, 256>>>(Uf_W, U_iou);

    // Leaves: iou = emb[wordid] @ W_iou^T
    sgemm_k<0><<<dim3(Bx * NLEAF / 128, GH3 / 128), 256>>>(
        W_iou, GH3, Xx, wordid, emb, 0, 0);
    leaf_node_k<<<(Bx * NLEAF * Hx + 255) / 256, 256>>>(b_iou, c0);

    // Tree levels (serial)
    for (int level = 8; level >= 0; level--) {
        int npar = 1 << level, ps = npar - 1;
        sgemm_k<1><<<dim3(npar, NC / 128), 256>>>(
            nullptr, NC, K2H, nullptr, nullptr, ps, level);
        level_node_k<<<((Bx << level) * Hx + 255) / 256, 256>>>(
            b_iou, Uf_b, ps, level);
    }

    // Attention + head
    q_k<<<Bx, 256>>>(Wmem);
    attn_k<<<Bx, 1024>>>();
    final_k<<<Bx, 256>>>(wh_W, wh_b, lin_W, lin_b, out);
}

// round 2
// speedup vs baseline: 1.9913x; 1.9913x over previous
#include <cuda_runtime.h>
#include <math.h>
#include <stdint.h>

#define Bx 128
#define Nx 1023
#define Hx 256
#define Xx 256
#define Cx 10
#define NLEAF 512
#define GH3 768      // 3*H
#define NC 1280      // 2H (f gates) + 3H (iou)
#define K2H 512      // 2*H

// ---- device-global scratch (no allocations allowed) ----
__device__ float g_h[(size_t)Bx * Nx * Hx];          // 134 MB
__device__ float g_c[(size_t)Bx * Nx * Hx];          // 134 MB
__device__ float g_scr[(size_t)Bx * NLEAF * GH3];    // 201 MB (reused per level)
__device__ float g_Wc[NC * K2H];                     // packed [Uf_W ; U_iou]
__device__ float g_q[Bx * Hx];
__device__ float g_ctx[Bx * Hx];

__device__ __forceinline__ float sigm(float x) { return 1.f / (1.f + expf(-x)); }

__device__ __forceinline__ uint32_t f2tf32(float x) {
    uint32_t r;
    asm("cvt.rna.tf32.f32 %0, %1;" : "=r"(r) : "f"(x));
    return r;
}

// ---- pack [Uf_W (512x512) ; U_iou (768x512)] into one 1280x512 matrix ----
__global__ void pack_wc_k(const float* __restrict__ Uf_W,
                          const float* __restrict__ U_iou) {
    int i = blockIdx.x * 256 + threadIdx.x;
    if (i >= NC * K2H) return;
    g_Wc[i] = (i < K2H * K2H) ? Uf_W[i] : U_iou[i - K2H * K2H];
}

// ===================================================================
// TF32 tensor-core GEMM: out[r][n] = sum_k A[r][k] * Wt[n][k]
// Block 128x128, 256 thr = 8 warps (2M x 4N), warp tile 64x32.
// K-chunk 16, double-buffered smem [row][k] padded to 20 (conflict-free).
// MODE 0: A row r=(b*512+l) -> emb[wordid[b,511+l]]   (K=256, N=768)
// MODE 1: A row r=(b*npar+pl) -> g_h[b, 2*(ps+pl)+1]  (K=512, N=1280, Wt=g_Wc)
// ===================================================================
template <int MODE>
__global__ __launch_bounds__(256, 2) void tgemm_k(
    const float* __restrict__ WtIn, int Ncols, int K,
    const int* __restrict__ wordid, const float* __restrict__ emb,
    int ps, int shift) {
    __shared__ uint32_t As[2][128][20];
    __shared__ uint32_t Bs[2][128][20];
    const float* Wt = (MODE == 1) ? (const float*)g_Wc : WtIn;
    const int tid = threadIdx.x;
    const int rowStart = blockIdx.x * 128, colStart = blockIdx.y * 128;
    // staging: thread handles one row, half the k-chunk
    const int sr = tid >> 1, sk = (tid & 1) * 8;

    const float* ap;
    {
        int r = rowStart + sr;
        if (MODE == 0) {
            int b = r >> 9, l = r & 511;
            int w = wordid[b * Nx + (NLEAF - 1) + l];
            ap = emb + (size_t)w * Xx;
        } else {
            int b = r >> shift, pl = r & ((1 << shift) - 1);
            ap = g_h + ((size_t)(b * Nx + 2 * (ps + pl) + 1)) * Hx;
        }
    }
    const float* bp = Wt + (size_t)(colStart + sr) * K;

    const int lane = tid & 31, warp = tid >> 5;
    const int warpM = warp >> 2, warpN = warp & 3;
    const int g = lane >> 2, tt = lane & 3;

    float acc[4][4][4];
#pragma unroll
    for (int mi = 0; mi < 4; mi++)
#pragma unroll
        for (int ni = 0; ni < 4; ni++)
#pragma unroll
            for (int cc = 0; cc < 4; cc++) acc[mi][ni][cc] = 0.f;

    // preload chunk 0
    {
        float4 va0 = *(const float4*)(ap + sk);
        float4 va1 = *(const float4*)(ap + sk + 4);
        float4 vb0 = *(const float4*)(bp + sk);
        float4 vb1 = *(const float4*)(bp + sk + 4);
        As[0][sr][sk + 0] = f2tf32(va0.x); As[0][sr][sk + 1] = f2tf32(va0.y);
        As[0][sr][sk + 2] = f2tf32(va0.z); As[0][sr][sk + 3] = f2tf32(va0.w);
        As[0][sr][sk + 4] = f2tf32(va1.x); As[0][sr][sk + 5] = f2tf32(va1.y);
        As[0][sr][sk + 6] = f2tf32(va1.z); As[0][sr][sk + 7] = f2tf32(va1.w);
        Bs[0][sr][sk + 0] = f2tf32(vb0.x); Bs[0][sr][sk + 1] = f2tf32(vb0.y);
        Bs[0][sr][sk + 2] = f2tf32(vb0.z); Bs[0][sr][sk + 3] = f2tf32(vb0.w);
        Bs[0][sr][sk + 4] = f2tf32(vb1.x); Bs[0][sr][sk + 5] = f2tf32(vb1.y);
        Bs[0][sr][sk + 6] = f2tf32(vb1.z); Bs[0][sr][sk + 7] = f2tf32(vb1.w);
    }
    __syncthreads();

    int st = 0;
    for (int k0 = 16; k0 <= K; k0 += 16) {
        float4 va0, va1, vb0, vb1;
        const bool pf = (k0 < K);
        if (pf) {
            va0 = *(const float4*)(ap + k0 + sk);
            va1 = *(const float4*)(ap + k0 + sk + 4);
            vb0 = *(const float4*)(bp + k0 + sk);
            vb1 = *(const float4*)(bp + k0 + sk + 4);
        }
#pragma unroll
        for (int ks = 0; ks < 2; ks++) {
            uint32_t a[4][4], b[4][2];
#pragma unroll
            for (int mi = 0; mi < 4; mi++) {
                int r0 = warpM * 64 + mi * 16 + g;
                a[mi][0] = As[st][r0][ks * 8 + tt];
                a[mi][1] = As[st][r0 + 8][ks * 8 + tt];
                a[mi][2] = As[st][r0][ks * 8 + tt + 4];
                a[mi][3] = As[st][r0 + 8][ks * 8 + tt + 4];
            }
#pragma unroll
            for (int ni = 0; ni < 4; ni++) {
                int c0 = warpN * 32 + ni * 8 + g;
                b[ni][0] = Bs[st][c0][ks * 8 + tt];
                b[ni][1] = Bs[st][c0][ks * 8 + tt + 4];
            }
#pragma unroll
            for (int mi = 0; mi < 4; mi++)
#pragma unroll
                for (int ni = 0; ni < 4; ni++) {
                    asm volatile(
                        "mma.sync.aligned.m16n8k8.row.col.f32.tf32.tf32.f32 "
                        "{%0,%1,%2,%3}, {%4,%5,%6,%7}, {%8,%9}, {%0,%1,%2,%3};"
                        : "+f"(acc[mi][ni][0]), "+f"(acc[mi][ni][1]),
                          "+f"(acc[mi][ni][2]), "+f"(acc[mi][ni][3])
                        : "r"(a[mi][0]), "r"(a[mi][1]), "r"(a[mi][2]), "r"(a[mi][3]),
                          "r"(b[ni][0]), "r"(b[ni][1]));
                }
        }
        if (pf) {
            int ns = st ^ 1;
            As[ns][sr][sk + 0] = f2tf32(va0.x); As[ns][sr][sk + 1] = f2tf32(va0.y);
            As[ns][sr][sk + 2] = f2tf32(va0.z); As[ns][sr][sk + 3] = f2tf32(va0.w);
            As[ns][sr][sk + 4] = f2tf32(va1.x); As[ns][sr][sk + 5] = f2tf32(va1.y);
            As[ns][sr][sk + 6] = f2tf32(va1.z); As[ns][sr][sk + 7] = f2tf32(va1.w);
            Bs[ns][sr][sk + 0] = f2tf32(vb0.x); Bs[ns][sr][sk + 1] = f2tf32(vb0.y);
            Bs[ns][sr][sk + 2] = f2tf32(vb0.z); Bs[ns][sr][sk + 3] = f2tf32(vb0.w);
            Bs[ns][sr][sk + 4] = f2tf32(vb1.x); Bs[ns][sr][sk + 5] = f2tf32(vb1.y);
            Bs[ns][sr][sk + 6] = f2tf32(vb1.z); Bs[ns][sr][sk + 7] = f2tf32(vb1.w);
        }
        __syncthreads();
        st ^= 1;
    }

#pragma unroll
    for (int mi = 0; mi < 4; mi++)
#pragma unroll
        for (int ni = 0; ni < 4; ni++) {
            int row = rowStart + warpM * 64 + mi * 16 + g;
            int colb = colStart + warpN * 32 + ni * 8 + tt * 2;
            float2 v01 = make_float2(acc[mi][ni][0], acc[mi][ni][1]);
            float2 v23 = make_float2(acc[mi][ni][2], acc[mi][ni][3]);
            *(float2*)(g_scr + (size_t)row * Ncols + colb) = v01;
            *(float2*)(g_scr + (size_t)(row + 8) * Ncols + colb) = v23;
        }
}

// ---- leaf epilogue: iou -> (h, c) at nodes 511..1022 ----
__global__ void leaf_node_k(const float* __restrict__ b_iou,
                            const float* __restrict__ c0) {
    int i = blockIdx.x * 256 + threadIdx.x;
    if (i >= Bx * NLEAF * Hx) return;
    int j = i & 255;
    int rl = i >> 8;              // b*512 + l
    int b = rl >> 9, l = rl & 511;
    const float* row = g_scr + (size_t)rl * GH3;
    float iv = row[j] + b_iou[j];
    float ov = row[256 + j] + b_iou[256 + j];
    float uv = row[512 + j] + b_iou[512 + j];
    size_t idx = ((size_t)(b * Nx + (NLEAF - 1) + l)) * Hx + j;
    float c = sigm(iv) * tanhf(uv) + c0[idx];
    float h = sigm(ov) * tanhf(c);
    g_c[idx] = c;
    g_h[idx] = h;
}

// ---- level epilogue: [f1,f2,iou] + child c -> parent (h, c) ----
__global__ void level_node_k(const float* __restrict__ b_iou,
                             const float* __restrict__ Uf_b, int ps, int shift) {
    int total = (Bx << shift) * Hx;
    int i = blockIdx.x * 256 + threadIdx.x;
    if (i >= total) return;
    int j = i & 255;
    int rl = i >> 8;                       // b*npar + pl
    int b = rl >> shift, pl = rl & ((1 << shift) - 1);
    const float* row = g_scr + (size_t)rl * NC;
    int p = ps + pl;
    size_t ci1 = ((size_t)(b * Nx + 2 * p + 1)) * Hx + j;
    float f1 = sigm(row[j] + Uf_b[j]);
    float f2 = sigm(row[256 + j] + Uf_b[256 + j]);
    float csum = f1 * g_c[ci1] + f2 * g_c[ci1 + Hx];
    float iv = row[512 + j] + b_iou[j];
    float ov = row[768 + j] + b_iou[256 + j];
    float uv = row[1024 + j] + b_iou[512 + j];
    float c = sigm(iv) * tanhf(uv) + csum;
    float h = sigm(ov) * tanhf(c);
    size_t pi = ((size_t)(b * Nx + p)) * Hx + j;
    g_c[pi] = c;
    g_h[pi] = h;
}

// ---- q[b] = Wmem^T @ h[b,0,:]  (scores factored: dec^T Wmem h = q . h) ----
__global__ void q_k(const float* __restrict__ Wmem) {
    int b = blockIdx.x, h = threadIdx.x;
    __shared__ float dec[256];
    dec[h] = g_h[((size_t)(b * Nx)) * Hx + h];
    __syncthreads();
    float s = 0.f;
#pragma unroll 4
    for (int g = 0; g < 256; g++) s += dec[g] * Wmem[g * 256 + h];
    g_q[b * Hx + h] = s;
}

// ---- per-batch fused scores + softmax + context ----
__global__ __launch_bounds__(1024) void attn_k() {
    __shared__ float q[256];
    __shared__ float sc[1024];
    __shared__ float red[32];
    __shared__ float ctxp[4][256];
    __shared__ float stat[2];
    int b = blockIdx.x, tid = threadIdx.x;
    int warp = tid >> 5, lane = tid & 31;
    if (tid < 256) q[tid] = g_q[b * Hx + tid];
    __syncthreads();
    const float* hb = g_h + (size_t)b * Nx * Hx;
    for (int n = warp; n < Nx; n += 32) {
        const float* hr = hb + (size_t)n * Hx;
        float s = 0.f;
#pragma unroll
        for (int kk = 0; kk < 8; kk++) s += q[lane + kk * 32] * hr[lane + kk * 32];
#pragma unroll
        for (int o = 16; o; o >>= 1) s += __shfl_xor_sync(0xffffffffu, s, o);
        if (lane == 0) sc[n] = s;
    }
    __syncthreads();
    float sraw = (tid < Nx) ? sc[tid] : -3.4e38f;
    float v = sraw;
#pragma unroll
    for (int o = 16; o; o >>= 1) v = fmaxf(v, __shfl_xor_sync(0xffffffffu, v, o));
    if (lane == 0) red[warp] = v;
    __syncthreads();
    if (warp == 0) {
        float m = red[lane];
#pragma unroll
        for (int o = 16; o; o >>= 1) m = fmaxf(m, __shfl_xor_sync(0xffffffffu, m, o));
        if (lane == 0) stat[0] = m;
    }
    __syncthreads();
    float m = stat[0];
    float e = (tid < Nx) ? expf(sraw - m) : 0.f;
    sc[tid] = e;  // own-slot overwrite; everyone else done reading others' scores
    float s = e;
#pragma unroll
    for (int o = 16; o; o >>= 1) s += __shfl_xor_sync(0xffffffffu, s, o);
    if (lane == 0) red[warp] = s;
    __syncthreads();
    if (warp == 0) {
        float S = red[lane];
#pragma unroll
        for (int o = 16; o; o >>= 1) S += __shfl_xor_sync(0xffffffffu, S, o);
        if (lane == 0) stat[1] = S;
    }
    __syncthreads();
    float Sinv = 1.f / stat[1];
    int grp = tid >> 8, j = tid & 255;
    float p = 0.f;
    for (int n = grp; n < Nx; n += 4) p += sc[n] * hb[(size_t)n * Hx + j];
    ctxp[grp][j] = p;
    __syncthreads();
    if (tid < 256) {
        g_ctx[b * Hx + tid] =
            (ctxp[0][tid] + ctxp[1][tid] + ctxp[2][tid] + ctxp[3][tid]) * Sinv;
    }
}

// ---- head: hid = relu(ctx @ wh_W^T + wh_b); out = hid @ lin_W^T + lin_b ----
__global__ void final_k(const float* __restrict__ wh_W,
                        const float* __restrict__ wh_b,
                        const float* __restrict__ lin_W,
                        const float* __restrict__ lin_b,
                        float* __restrict__ out) {
    int b = blockIdx.x, tid = threadIdx.x;
    int warp = tid >> 5, lane = tid & 31;
    __shared__ float ctx[256];
    __shared__ float hid[256];
    ctx[tid] = g_ctx[b * Hx + tid];
    __syncthreads();
    for (int h = warp; h < 256; h += 8) {
        const float* wr = wh_W + (size_t)h * 256;
        float s = 0.f;
#pragma unroll
        for (int kk = 0; kk < 8; kk++) s += ctx[lane + kk * 32] * wr[lane + kk * 32];
#pragma unroll
        for (int o = 16; o; o >>= 1) s += __shfl_xor_sync(0xffffffffu, s, o);
        if (lane == 0) hid[h] = fmaxf(s + wh_b[h], 0.f);
    }
    __syncthreads();
    if (warp == 0) {
        for (int cc = 0; cc < Cx; cc++) {
            const float* lr = lin_W + (size_t)cc * 256;
            float s = 0.f;
#pragma unroll
            for (int kk = 0; kk < 8; kk++) s += hid[lane + kk * 32] * lr[lane + kk * 32];
#pragma unroll
            for (int o = 16; o; o >>= 1) s += __shfl_xor_sync(0xffffffffu, s, o);
            if (lane == 0) out[b * Cx + cc] = s + lin_b[cc];
        }
    }
}

extern "C" void kernel_launch(void* const* d_in, const int* in_sizes, int n_in,
                              void* d_out, int out_size) {
    const int* wordid   = (const int*)d_in[0];
    // d_in[1] = h0 (unused: every node is overwritten)
    const float* c0     = (const float*)d_in[2];
    const float* emb    = (const float*)d_in[3];
    const float* W_iou  = (const float*)d_in[4];
    const float* U_iou  = (const float*)d_in[5];
    const float* b_iou  = (const float*)d_in[6];
    const float* Uf_W   = (const float*)d_in[7];
    const float* Uf_b   = (const float*)d_in[8];
    const float* Wmem   = (const float*)d_in[9];
    const float* wh_W   = (const float*)d_in[10];
    const float* wh_b   = (const float*)d_in[11];
    const float* lin_W  = (const float*)d_in[12];
    const float* lin_b  = (const float*)d_in[13];
    float* out = (float*)d_out;
    (void)in_sizes; (void)n_in; (void)out_size;

    pack_wc_k<<<(NC * K2H + 255) / 256, 256>>>(Uf_W, U_iou);

    // Leaves: iou = emb[wordid] @ W_iou^T  (rows = 128*512, cols = 768, K = 256)
    tgemm_k<0><<<dim3(Bx * NLEAF / 128, GH3 / 128), 256>>>(
        W_iou, GH3, Xx, wordid, emb, 0, 0);
    leaf_node_k<<<(Bx * NLEAF * Hx + 255) / 256, 256>>>(b_iou, c0);

    // Tree levels (serial)
    for (int level = 8; level >= 0; level--) {
        int npar = 1 << level, ps = npar - 1;
        tgemm_k<1><<<dim3(npar, NC / 128), 256>>>(
            nullptr, NC, K2H, nullptr, nullptr, ps, level);
        level_node_k<<<((Bx << level) * Hx + 255) / 256, 256>>>(
            b_iou, Uf_b, ps, level);
    }

    // Attention + head
    q_k<<<Bx, 256>>>(Wmem);
    attn_k<<<Bx, 1024>>>();
    final_k<<<Bx, 256>>>(wh_W, wh_b, lin_W, lin_b, out);
}

// round 4
// speedup vs baseline: 2.6177x; 1.3146x over previous
#include <cuda_runtime.h>
#include <cuda_fp16.h>
#include <math.h>
#include <stdint.h>

#define Bx 128
#define Nx 1023
#define Hx 256
#define Xx 256
#define Cx 10
#define NLEAF 512
#define GH3 768      // 3*H
#define NC 1280      // 2H (f gates) + 3H (iou)
#define K2H 512      // 2*H

// ---- device-global scratch (no allocations allowed) ----
__device__ float g_h[(size_t)Bx * Nx * Hx];          // 134 MB
__device__ float g_c[(size_t)Bx * Nx * Hx];          // 134 MB
__device__ float g_scr[(size_t)Bx * NLEAF * GH3];    // 201 MB (reused per level)
__device__ float g_Wc[NC * K2H];                     // packed [Uf_W ; U_iou]
__device__ float g_q[Bx * Hx];
__device__ float g_ctx[Bx * Hx];

__device__ __forceinline__ float sigm(float x) { return 1.f / (1.f + expf(-x)); }

#define LDSM4(r0, r1, r2, r3, addr)                                          \
    asm volatile("ldmatrix.sync.aligned.m8n8.x4.shared.b16 {%0,%1,%2,%3}, [%4];" \
                 : "=r"(r0), "=r"(r1), "=r"(r2), "=r"(r3) : "r"(addr))

#define HMMA(d, a, b0, b1)                                                   \
    asm volatile(                                                            \
        "mma.sync.aligned.m16n8k16.row.col.f32.f16.f16.f32 "                 \
        "{%0,%1,%2,%3}, {%4,%5,%6,%7}, {%8,%9}, {%0,%1,%2,%3};"              \
        : "+f"(d[0]), "+f"(d[1]), "+f"(d[2]), "+f"(d[3])                     \
        : "r"(a[0]), "r"(a[1]), "r"(a[2]), "r"(a[3]), "r"(b0), "r"(b1))

__device__ __forceinline__ uint32_t smem_u32(const void* p) {
    uint32_t a;
    asm("{ .reg .u64 t; cvta.to.shared.u64 t, %1; cvt.u32.u64 %0, t; }"
        : "=r"(a) : "l"(p));
    return a;
}

__device__ __forceinline__ uint32_t packh2(float x, float y) {
    __half2 h = __floats2half2_rn(x, y);
    return *(uint32_t*)&h;
}

// ---- pack [Uf_W (512x512) ; U_iou (768x512)] into one 1280x512 matrix ----
__global__ void pack_wc_k(const float* __restrict__ Uf_W,
                          const float* __restrict__ U_iou) {
    int i = blockIdx.x * 256 + threadIdx.x;
    if (i >= NC * K2H) return;
    g_Wc[i] = (i < K2H * K2H) ? Uf_W[i] : U_iou[i - K2H * K2H];
}

// ===================================================================
// FP16 tensor-core GEMM via mma.m16n8k16 + ldmatrix.
// out[r][n] = sum_k A[r][k] * Wt[n][k]
// Block 128x128, 256 thr = 8 warps (2M x 4N), warp tile 64x32.
// K-chunk 32 halves, double-buffered smem rows padded to 40 halves
// (80B stride -> conflict-free ldmatrix phases).
// MODE 0: A row r=(b*512+l) -> emb[wordid[b,511+l]]   (K=256, N=768)
// MODE 1: A row r=(b*npar+pl) -> g_h[b, 2*(ps+pl)+1]  (K=512, N=1280, Wt=g_Wc)
// ===================================================================
#define ROWB 80          // bytes per padded smem row (40 halves)
#define BUFB (128 * ROWB)  // 10240 B per buffer

template <int MODE>
__global__ __launch_bounds__(256, 2) void hgemm_k(
    const float* __restrict__ WtIn, int Ncols, int K,
    const int* __restrict__ wordid, const float* __restrict__ emb,
    int ps, int shift) {
    __shared__ __half As[2][128][40];
    __shared__ __half Bs[2][128][40];
    const float* Wt = (MODE == 1) ? (const float*)g_Wc : WtIn;
    const int tid = threadIdx.x;
    const int rowStart = blockIdx.x * 128, colStart = blockIdx.y * 128;
    const int lane = tid & 31, warp = tid >> 5;
    const int warpM = warp >> 2, warpN = warp & 3;

    // staging: thread -> row tid>>1, k-half (tid&1)*16 of the 32-wide chunk
    const int sr = tid >> 1, kh = (tid & 1) * 16;
    const float* ap;
    {
        int r = rowStart + sr;
        if (MODE == 0) {
            int b = r >> 9, l = r & 511;
            int w = wordid[b * Nx + (NLEAF - 1) + l];
            ap = emb + (size_t)w * Xx;
        } else {
            int b = r >> shift, pl = r & ((1 << shift) - 1);
            ap = g_h + ((size_t)(b * Nx + 2 * (ps + pl) + 1)) * Hx;
        }
    }
    const float* bp = Wt + (size_t)(colStart + sr) * K;

    const uint32_t aSm = smem_u32(&As[0][0][0]);
    const uint32_t bSm = smem_u32(&Bs[0][0][0]);
    // ldmatrix lane->address bases (byte offsets inside one buffer)
    const int aRow = warpM * 64 + (lane & 7) + ((lane >> 3) & 1) * 8;
    const int aK = (lane >> 4) * 8;               // halves
    const int bRow = warpN * 32 + (lane & 7) + ((lane >> 4) & 1) * 8;
    const int bK = ((lane >> 3) & 1) * 8;
    const uint32_t aAddr0 = aSm + aRow * ROWB + aK * 2;
    const uint32_t bAddr0 = bSm + bRow * ROWB + bK * 2;

    float acc[4][4][4];
#pragma unroll
    for (int mi = 0; mi < 4; mi++)
#pragma unroll
        for (int ni = 0; ni < 4; ni++)
#pragma unroll
            for (int cc = 0; cc < 4; cc++) acc[mi][ni][cc] = 0.f;

    // stage chunk 0 into buffer 0
    {
        float4 v0 = *(const float4*)(ap + kh);
        float4 v1 = *(const float4*)(ap + kh + 4);
        float4 v2 = *(const float4*)(ap + kh + 8);
        float4 v3 = *(const float4*)(ap + kh + 12);
        uint4 u0 = make_uint4(packh2(v0.x, v0.y), packh2(v0.z, v0.w),
                              packh2(v1.x, v1.y), packh2(v1.z, v1.w));
        uint4 u1 = make_uint4(packh2(v2.x, v2.y), packh2(v2.z, v2.w),
                              packh2(v3.x, v3.y), packh2(v3.z, v3.w));
        *(uint4*)&As[0][sr][kh] = u0;
        *(uint4*)&As[0][sr][kh + 8] = u1;
        float4 w0 = *(const float4*)(bp + kh);
        float4 w1 = *(const float4*)(bp + kh + 4);
        float4 w2 = *(const float4*)(bp + kh + 8);
        float4 w3 = *(const float4*)(bp + kh + 12);
        uint4 s0 = make_uint4(packh2(w0.x, w0.y), packh2(w0.z, w0.w),
                              packh2(w1.x, w1.y), packh2(w1.z, w1.w));
        uint4 s1 = make_uint4(packh2(w2.x, w2.y), packh2(w2.z, w2.w),
                              packh2(w3.x, w3.y), packh2(w3.z, w3.w));
        *(uint4*)&Bs[0][sr][kh] = s0;
        *(uint4*)&Bs[0][sr][kh + 8] = s1;
    }
    __syncthreads();

    const int nch = K / 32;
    int st = 0;
    for (int ci = 0; ci < nch; ci++) {
        const bool pf = (ci + 1 < nch);
        float4 v0, v1, v2, v3, w0, w1, w2, w3;
        if (pf) {
            const float* a2 = ap + (ci + 1) * 32 + kh;
            const float* b2 = bp + (ci + 1) * 32 + kh;
            v0 = *(const float4*)(a2);
            v1 = *(const float4*)(a2 + 4);
            v2 = *(const float4*)(a2 + 8);
            v3 = *(const float4*)(a2 + 12);
            w0 = *(const float4*)(b2);
            w1 = *(const float4*)(b2 + 4);
            w2 = *(const float4*)(b2 + 8);
            w3 = *(const float4*)(b2 + 12);
        }
        const uint32_t ab = aAddr0 + st * BUFB;
        const uint32_t bb = bAddr0 + st * BUFB;
#pragma unroll
        for (int ks = 0; ks < 2; ks++) {
            uint32_t a[4][4], b[2][4];
#pragma unroll
            for (int mi = 0; mi < 4; mi++)
                LDSM4(a[mi][0], a[mi][1], a[mi][2], a[mi][3],
                      ab + mi * (16 * ROWB) + ks * 32);
#pragma unroll
            for (int nt = 0; nt < 2; nt++)
                LDSM4(b[nt][0], b[nt][1], b[nt][2], b[nt][3],
                      bb + nt * (16 * ROWB) + ks * 32);
#pragma unroll
            for (int mi = 0; mi < 4; mi++)
#pragma unroll
                for (int n8 = 0; n8 < 4; n8++) {
                    HMMA(acc[mi][n8], a[mi], b[n8 >> 1][(n8 & 1) * 2],
                         b[n8 >> 1][(n8 & 1) * 2 + 1]);
                }
        }
        if (pf) {
            int ns = st ^ 1;
            uint4 u0 = make_uint4(packh2(v0.x, v0.y), packh2(v0.z, v0.w),
                                  packh2(v1.x, v1.y), packh2(v1.z, v1.w));
            uint4 u1 = make_uint4(packh2(v2.x, v2.y), packh2(v2.z, v2.w),
                                  packh2(v3.x, v3.y), packh2(v3.z, v3.w));
            *(uint4*)&As[ns][sr][kh] = u0;
            *(uint4*)&As[ns][sr][kh + 8] = u1;
            uint4 s0 = make_uint4(packh2(w0.x, w0.y), packh2(w0.z, w0.w),
                                  packh2(w1.x, w1.y), packh2(w1.z, w1.w));
            uint4 s1 = make_uint4(packh2(w2.x, w2.y), packh2(w2.z, w2.w),
                                  packh2(w3.x, w3.y), packh2(w3.z, w3.w));
            *(uint4*)&Bs[ns][sr][kh] = s0;
            *(uint4*)&Bs[ns][sr][kh + 8] = s1;
        }
        __syncthreads();
        st ^= 1;
    }

    const int g = lane >> 2, tt = lane & 3;
#pragma unroll
    for (int mi = 0; mi < 4; mi++)
#pragma unroll
        for (int ni = 0; ni < 4; ni++) {
            int row = rowStart + warpM * 64 + mi * 16 + g;
            int colb = colStart + warpN * 32 + ni * 8 + tt * 2;
            float2 v01 = make_float2(acc[mi][ni][0], acc[mi][ni][1]);
            float2 v23 = make_float2(acc[mi][ni][2], acc[mi][ni][3]);
            *(float2*)(g_scr + (size_t)row * Ncols + colb) = v01;
            *(float2*)(g_scr + (size_t)(row + 8) * Ncols + colb) = v23;
        }
}

// ---- leaf epilogue: iou -> (h, c) at nodes 511..1022 ----
__global__ void leaf_node_k(const float* __restrict__ b_iou,
                            const float* __restrict__ c0) {
    int i = blockIdx.x * 256 + threadIdx.x;
    if (i >= Bx * NLEAF * Hx) return;
    int j = i & 255;
    int rl = i >> 8;              // b*512 + l
    int b = rl >> 9, l = rl & 511;
    const float* row = g_scr + (size_t)rl * GH3;
    float iv = row[j] + b_iou[j];
    float ov = row[256 + j] + b_iou[256 + j];
    float uv = row[512 + j] + b_iou[512 + j];
    size_t idx = ((size_t)(b * Nx + (NLEAF - 1) + l)) * Hx + j;
    float c = sigm(iv) * tanhf(uv) + c0[idx];
    float h = sigm(ov) * tanhf(c);
    g_c[idx] = c;
    g_h[idx] = h;
}

// ---- level epilogue: [f1,f2,iou] + child c -> parent (h, c) ----
__global__ void level_node_k(const float* __restrict__ b_iou,
                             const float* __restrict__ Uf_b, int ps, int shift) {
    int total = (Bx << shift) * Hx;
    int i = blockIdx.x * 256 + threadIdx.x;
    if (i >= total) return;
    int j = i & 255;
    int rl = i >> 8;                       // b*npar + pl
    int b = rl >> shift, pl = rl & ((1 << shift) - 1);
    const float* row = g_scr + (size_t)rl * NC;
    int p = ps + pl;
    size_t ci1 = ((size_t)(b * Nx + 2 * p + 1)) * Hx + j;
    float f1 = sigm(row[j] + Uf_b[j]);
    float f2 = sigm(row[256 + j] + Uf_b[256 + j]);
    float csum = f1 * g_c[ci1] + f2 * g_c[ci1 + Hx];
    float iv = row[512 + j] + b_iou[j];
    float ov = row[768 + j] + b_iou[256 + j];
    float uv = row[1024 + j] + b_iou[512 + j];
    float c = sigm(iv) * tanhf(uv) + csum;
    float h = sigm(ov) * tanhf(c);
    size_t pi = ((size_t)(b * Nx + p)) * Hx + j;
    g_c[pi] = c;
    g_h[pi] = h;
}

// ---- q[b] = Wmem^T @ h[b,0,:]  (scores factored: dec^T Wmem h = q . h) ----
__global__ void q_k(const float* __restrict__ Wmem) {
    int b = blockIdx.x, h = threadIdx.x;
    __shared__ float dec[256];
    dec[h] = g_h[((size_t)(b * Nx)) * Hx + h];
    __syncthreads();
    float s = 0.f;
#pragma unroll 4
    for (int g = 0; g < 256; g++) s += dec[g] * Wmem[g * 256 + h];
    g_q[b * Hx + h] = s;
}

// ---- per-batch fused scores + softmax + context ----
__global__ __launch_bounds__(1024) void attn_k() {
    __shared__ float q[256];
    __shared__ float sc[1024];
    __shared__ float red[32];
    __shared__ float ctxp[4][256];
    __shared__ float stat[2];
    int b = blockIdx.x, tid = threadIdx.x;
    int warp = tid >> 5, lane = tid & 31;
    if (tid < 256) q[tid] = g_q[b * Hx + tid];
    __syncthreads();
    const float* hb = g_h + (size_t)b * Nx * Hx;
    for (int n = warp; n < Nx; n += 32) {
        const float* hr = hb + (size_t)n * Hx;
        float s = 0.f;
#pragma unroll
        for (int kk = 0; kk < 8; kk++) s += q[lane + kk * 32] * hr[lane + kk * 32];
#pragma unroll
        for (int o = 16; o; o >>= 1) s += __shfl_xor_sync(0xffffffffu, s, o);
        if (lane == 0) sc[n] = s;
    }
    __syncthreads();
    float sraw = (tid < Nx) ? sc[tid] : -3.4e38f;
    float v = sraw;
#pragma unroll
    for (int o = 16; o; o >>= 1) v = fmaxf(v, __shfl_xor_sync(0xffffffffu, v, o));
    if (lane == 0) red[warp] = v;
    __syncthreads();
    if (warp == 0) {
        float m = red[lane];
#pragma unroll
        for (int o = 16; o; o >>= 1) m = fmaxf(m, __shfl_xor_sync(0xffffffffu, m, o));
        if (lane == 0) stat[0] = m;
    }
    __syncthreads();
    float m = stat[0];
    float e = (tid < Nx) ? expf(sraw - m) : 0.f;
    sc[tid] = e;
    float s = e;
#pragma unroll
    for (int o = 16; o; o >>= 1) s += __shfl_xor_sync(0xffffffffu, s, o);
    if (lane == 0) red[warp] = s;
    __syncthreads();
    if (warp == 0) {
        float S = red[lane];
#pragma unroll
        for (int o = 16; o; o >>= 1) S += __shfl_xor_sync(0xffffffffu, S, o);
        if (lane == 0) stat[1] = S;
    }
    __syncthreads();
    float Sinv = 1.f / stat[1];
    int grp = tid >> 8, j = tid & 255;
    float p = 0.f;
    for (int n = grp; n < Nx; n += 4) p += sc[n] * hb[(size_t)n * Hx + j];
    ctxp[grp][j] = p;
    __syncthreads();
    if (tid < 256) {
        g_ctx[b * Hx + tid] =
            (ctxp[0][tid] + ctxp[1][tid] + ctxp[2][tid] + ctxp[3][tid]) * Sinv;
    }
}

// ---- head: hid = relu(ctx @ wh_W^T + wh_b); out = hid @ lin_W^T + lin_b ----
__global__ void final_k(const float* __restrict__ wh_W,
                        const float* __restrict__ wh_b,
                        const float* __restrict__ lin_W,
                        const float* __restrict__ lin_b,
                        float* __restrict__ out) {
    int b = blockIdx.x, tid = threadIdx.x;
    int warp = tid >> 5, lane = tid & 31;
    __shared__ float ctx[256];
    __shared__ float hid[256];
    ctx[tid] = g_ctx[b * Hx + tid];
    __syncthreads();
    for (int h = warp; h < 256; h += 8) {
        const float* wr = wh_W + (size_t)h * 256;
        float s = 0.f;
#pragma unroll
        for (int kk = 0; kk < 8; kk++) s += ctx[lane + kk * 32] * wr[lane + kk * 32];
#pragma unroll
        for (int o = 16; o; o >>= 1) s += __shfl_xor_sync(0xffffffffu, s, o);
        if (lane == 0) hid[h] = fmaxf(s + wh_b[h], 0.f);
    }
    __syncthreads();
    if (warp == 0) {
        for (int cc = 0; cc < Cx; cc++) {
            const float* lr = lin_W + (size_t)cc * 256;
            float s = 0.f;
#pragma unroll
            for (int kk = 0; kk < 8; kk++) s += hid[lane + kk * 32] * lr[lane + kk * 32];
#pragma unroll
            for (int o = 16; o; o >>= 1) s += __shfl_xor_sync(0xffffffffu, s, o);
            if (lane == 0) out[b * Cx + cc] = s + lin_b[cc];
        }
    }
}

extern "C" void kernel_launch(void* const* d_in, const int* in_sizes, int n_in,
                              void* d_out, int out_size) {
    const int* wordid   = (const int*)d_in[0];
    // d_in[1] = h0 (unused: every node is overwritten)
    const float* c0     = (const float*)d_in[2];
    const float* emb    = (const float*)d_in[3];
    const float* W_iou  = (const float*)d_in[4];
    const float* U_iou  = (const float*)d_in[5];
    const float* b_iou  = (const float*)d_in[6];
    const float* Uf_W   = (const float*)d_in[7];
    const float* Uf_b   = (const float*)d_in[8];
    const float* Wmem   = (const float*)d_in[9];
    const float* wh_W   = (const float*)d_in[10];
    const float* wh_b   = (const float*)d_in[11];
    const float* lin_W  = (const float*)d_in[12];
    const float* lin_b  = (const float*)d_in[13];
    float* out = (float*)d_out;
    (void)in_sizes; (void)n_in; (void)out_size;

    pack_wc_k<<<(NC * K2H + 255) / 256, 256>>>(Uf_W, U_iou);

    // Leaves: iou = emb[wordid] @ W_iou^T  (M=65536, N=768, K=256)
    hgemm_k<0><<<dim3(Bx * NLEAF / 128, GH3 / 128), 256>>>(
        W_iou, GH3, Xx, wordid, emb, 0, 0);
    leaf_node_k<<<(Bx * NLEAF * Hx + 255) / 256, 256>>>(b_iou, c0);

    // Tree levels (serial)
    for (int level = 8; level >= 0; level--) {
        int npar = 1 << level, ps = npar - 1;
        hgemm_k<1><<<dim3(npar, NC / 128), 256>>>(
            nullptr, NC, K2H, nullptr, nullptr, ps, level);
        level_node_k<<<((Bx << level) * Hx + 255) / 256, 256>>>(
            b_iou, Uf_b, ps, level);
    }

    // Attention + head
    q_k<<<Bx, 256>>>(Wmem);
    attn_k<<<Bx, 1024>>>();
    final_k<<<Bx, 256>>>(wh_W, wh_b, lin_W, lin_b, out);
}

// round 5
// speedup vs baseline: 2.8553x; 1.0908x over previous
#include <cuda_runtime.h>
#include <cuda_fp16.h>
#include <math.h>
#include <stdint.h>

#define Bx 128
#define Nx 1023
#define Hx 256
#define Xx 256
#define Cx 10
#define Vx 32000
#define NLEAF 512
#define GH3 768      // 3*H
#define NC 1280      // 2H (f gates) + 3H (iou)
#define K2H 512      // 2*H

// ---- device-global scratch (no allocations allowed) ----
__device__ float g_h[(size_t)Bx * Nx * Hx];           // 134 MB (fp32, attention)
__device__ __half g_h16[(size_t)Bx * Nx * Hx];        // 67 MB (GEMM A operand)
__device__ float g_c[(size_t)Bx * Nx * Hx];           // 134 MB
__device__ float g_scr[(size_t)Bx * NLEAF * GH3];     // 201 MB (per-level reuse)
__device__ __half g_emb16[(size_t)Vx * Xx];           // 16 MB
__device__ __half g_Wc16[NC * K2H];                   // packed [Uf_W ; U_iou] fp16
__device__ __half g_Wiou16[GH3 * Xx];
__device__ float g_q[Bx * Hx];
__device__ float g_ctx[Bx * Hx];

__device__ __forceinline__ float sigm(float x) { return 1.f / (1.f + expf(-x)); }

#define LDSM4(r0, r1, r2, r3, addr)                                          \
    asm volatile("ldmatrix.sync.aligned.m8n8.x4.shared.b16 {%0,%1,%2,%3}, [%4];" \
                 : "=r"(r0), "=r"(r1), "=r"(r2), "=r"(r3) : "r"(addr))

#define HMMA(d, a, b0, b1)                                                   \
    asm volatile(                                                            \
        "mma.sync.aligned.m16n8k16.row.col.f32.f16.f16.f32 "                 \
        "{%0,%1,%2,%3}, {%4,%5,%6,%7}, {%8,%9}, {%0,%1,%2,%3};"              \
        : "+f"(d[0]), "+f"(d[1]), "+f"(d[2]), "+f"(d[3])                     \
        : "r"(a[0]), "r"(a[1]), "r"(a[2]), "r"(a[3]), "r"(b0), "r"(b1))

#define CP16(dst, src)                                                       \
    asm volatile("cp.async.cg.shared.global [%0], [%1], 16;" ::"r"(dst),     \
                 "l"(src))
#define CPCOMMIT() asm volatile("cp.async.commit_group;")
#define CPWAIT(n) asm volatile("cp.async.wait_group %0;" ::"n"(n))

__device__ __forceinline__ uint32_t smem_u32(const void* p) {
    uint32_t a;
    asm("{ .reg .u64 t; cvta.to.shared.u64 t, %1; cvt.u32.u64 %0, t; }"
        : "=r"(a) : "l"(p));
    return a;
}

// ---- fp16 mirror setup ----
__global__ void emb16_k(const float* __restrict__ emb) {
    int i = blockIdx.x * 256 + threadIdx.x;
    if (i < Vx * Xx) g_emb16[i] = __float2half(emb[i]);
}
__global__ void wiou16_k(const float* __restrict__ W_iou) {
    int i = blockIdx.x * 256 + threadIdx.x;
    if (i < GH3 * Xx) g_Wiou16[i] = __float2half(W_iou[i]);
}
__global__ void wc16_k(const float* __restrict__ Uf_W,
                       const float* __restrict__ U_iou) {
    int i = blockIdx.x * 256 + threadIdx.x;
    if (i >= NC * K2H) return;
    float v = (i < K2H * K2H) ? Uf_W[i] : U_iou[i - K2H * K2H];
    g_Wc16[i] = __float2half(v);
}

// ===================================================================
// FP16 tensor GEMM: block 128x256, 8 warps (2M x 4N), warp tile 64x64.
// K-chunk 32, 2-stage cp.async pipeline, smem rows padded to 40 halves.
// out[r][n] = sum_k A[r][k] * Wt[n][k]  -> g_scr (fp32)
// MODE 0: A row r=(b*512+l) -> g_emb16[wordid[b,511+l]]  (K=256, Wt=g_Wiou16)
// MODE 1: A row r=(b*npar+pl) -> g_h16[b, 2*(ps+pl)+1]   (K=512, Wt=g_Wc16)
// ===================================================================
#define ROWB 80
#define ABYTES (128 * ROWB)                 // 10240
#define BUFBYTES ((128 + 256) * ROWB)       // 30720
#define SMEM_GEMM (2 * BUFBYTES)            // 61440

template <int MODE>
__global__ __launch_bounds__(256, 1) void hgemm_k(
    int Ncols, int K, const int* __restrict__ wordid, int ps, int shift) {
    extern __shared__ char smem[];
    const uint32_t sb = smem_u32(smem);
    const int tid = threadIdx.x, lane = tid & 31, warp = tid >> 5;
    const int rowStart = blockIdx.x * 128, colStart = blockIdx.y * 256;
    const int warpM = warp >> 2, warpN = warp & 3;

    // staging: A row tid>>1 (16-half slice), B row tid (32 halves)
    const int sr = tid >> 1, kh = (tid & 1) * 16;
    const __half* ap;
    {
        int r = rowStart + sr;
        if (MODE == 0) {
            int b = r >> 9, l = r & 511;
            int w = wordid[b * Nx + (NLEAF - 1) + l];
            ap = g_emb16 + (size_t)w * Xx + kh;
        } else {
            int b = r >> shift, pl = r & ((1 << shift) - 1);
            ap = g_h16 + ((size_t)(b * Nx + 2 * (ps + pl) + 1)) * Hx + kh;
        }
    }
    const __half* bp =
        (MODE == 0 ? (const __half*)g_Wiou16 : (const __half*)g_Wc16) +
        (size_t)(colStart + tid) * K;
    const uint32_t adst0 = sb + sr * ROWB + kh * 2;
    const uint32_t bdst0 = sb + ABYTES + tid * ROWB;

    // ldmatrix bases
    const int aRow = warpM * 64 + (lane & 7) + ((lane >> 3) & 1) * 8;
    const int aK = (lane >> 4) * 8;
    const int bRow = warpN * 64 + (lane & 7) + ((lane >> 4) & 1) * 8;
    const int bK = ((lane >> 3) & 1) * 8;
    const uint32_t aA0 = sb + aRow * ROWB + aK * 2;
    const uint32_t bA0 = sb + ABYTES + bRow * ROWB + bK * 2;

    float acc[4][8][4];
#pragma unroll
    for (int mi = 0; mi < 4; mi++)
#pragma unroll
        for (int ni = 0; ni < 8; ni++)
#pragma unroll
            for (int cc = 0; cc < 4; cc++) acc[mi][ni][cc] = 0.f;

    // prologue: stage chunk 0 into buf 0
    {
        CP16(adst0, ap); CP16(adst0 + 16, ap + 8);
        CP16(bdst0, bp); CP16(bdst0 + 16, bp + 8);
        CP16(bdst0 + 32, bp + 16); CP16(bdst0 + 48, bp + 24);
        CPCOMMIT();
    }

    const int nch = K / 32;
    for (int ci = 0; ci < nch; ci++) {
        if (ci + 1 < nch) {
            const int nb = (ci + 1) & 1;
            const uint32_t ad = adst0 + nb * BUFBYTES;
            const uint32_t bd = bdst0 + nb * BUFBYTES;
            const __half* ag = ap + (ci + 1) * 32;
            const __half* bg = bp + (ci + 1) * 32;
            CP16(ad, ag); CP16(ad + 16, ag + 8);
            CP16(bd, bg); CP16(bd + 16, bg + 8);
            CP16(bd + 32, bg + 16); CP16(bd + 48, bg + 24);
            CPCOMMIT();
            CPWAIT(1);
        } else {
            CPWAIT(0);
        }
        __syncthreads();
        const int st = ci & 1;
        const uint32_t ab = aA0 + st * BUFBYTES;
        const uint32_t bb = bA0 + st * BUFBYTES;
#pragma unroll
        for (int ks = 0; ks < 2; ks++) {
            uint32_t a[4][4], b[4][4];
#pragma unroll
            for (int mi = 0; mi < 4; mi++)
                LDSM4(a[mi][0], a[mi][1], a[mi][2], a[mi][3],
                      ab + mi * (16 * ROWB) + ks * 32);
#pragma unroll
            for (int nt = 0; nt < 4; nt++)
                LDSM4(b[nt][0], b[nt][1], b[nt][2], b[nt][3],
                      bb + nt * (16 * ROWB) + ks * 32);
#pragma unroll
            for (int mi = 0; mi < 4; mi++)
#pragma unroll
                for (int ni = 0; ni < 8; ni++)
                    HMMA(acc[mi][ni], a[mi], b[ni >> 1][(ni & 1) * 2],
                         b[ni >> 1][(ni & 1) * 2 + 1]);
        }
        __syncthreads();
    }

    const int g = lane >> 2, tt = lane & 3;
#pragma unroll
    for (int mi = 0; mi < 4; mi++)
#pragma unroll
        for (int ni = 0; ni < 8; ni++) {
            int row = rowStart + warpM * 64 + mi * 16 + g;
            int colb = colStart + warpN * 64 + ni * 8 + tt * 2;
            *(float2*)(g_scr + (size_t)row * Ncols + colb) =
                make_float2(acc[mi][ni][0], acc[mi][ni][1]);
            *(float2*)(g_scr + (size_t)(row + 8) * Ncols + colb) =
                make_float2(acc[mi][ni][2], acc[mi][ni][3]);
        }
}

// ---- leaf epilogue: iou -> (h, c) at nodes 511..1022 ----
__global__ void leaf_node_k(const float* __restrict__ b_iou,
                            const float* __restrict__ c0) {
    int i = blockIdx.x * 256 + threadIdx.x;
    if (i >= Bx * NLEAF * Hx) return;
    int j = i & 255;
    int rl = i >> 8;              // b*512 + l
    int b = rl >> 9, l = rl & 511;
    const float* row = g_scr + (size_t)rl * GH3;
    float iv = row[j] + b_iou[j];
    float ov = row[256 + j] + b_iou[256 + j];
    float uv = row[512 + j] + b_iou[512 + j];
    size_t idx = ((size_t)(b * Nx + (NLEAF - 1) + l)) * Hx + j;
    float c = sigm(iv) * tanhf(uv) + c0[idx];
    float h = sigm(ov) * tanhf(c);
    g_c[idx] = c;
    g_h[idx] = h;
    g_h16[idx] = __float2half(h);
}

// ---- level epilogue: [f1,f2,iou] + child c -> parent (h, c) ----
__global__ void level_node_k(const float* __restrict__ b_iou,
                             const float* __restrict__ Uf_b, int ps, int shift) {
    int total = (Bx << shift) * Hx;
    int i = blockIdx.x * 256 + threadIdx.x;
    if (i >= total) return;
    int j = i & 255;
    int rl = i >> 8;                       // b*npar + pl
    int b = rl >> shift, pl = rl & ((1 << shift) - 1);
    const float* row = g_scr + (size_t)rl * NC;
    int p = ps + pl;
    size_t ci1 = ((size_t)(b * Nx + 2 * p + 1)) * Hx + j;
    float f1 = sigm(row[j] + Uf_b[j]);
    float f2 = sigm(row[256 + j] + Uf_b[256 + j]);
    float csum = f1 * g_c[ci1] + f2 * g_c[ci1 + Hx];
    float iv = row[512 + j] + b_iou[j];
    float ov = row[768 + j] + b_iou[256 + j];
    float uv = row[1024 + j] + b_iou[512 + j];
    float c = sigm(iv) * tanhf(uv) + csum;
    float h = sigm(ov) * tanhf(c);
    size_t pi = ((size_t)(b * Nx + p)) * Hx + j;
    g_c[pi] = c;
    g_h[pi] = h;
    g_h16[pi] = __float2half(h);
}

// ---- q[b] = Wmem^T @ h[b,0,:]  (scores factored: dec^T Wmem h = q . h) ----
__global__ void q_k(const float* __restrict__ Wmem) {
    int b = blockIdx.x, h = threadIdx.x;
    __shared__ float dec[256];
    dec[h] = g_h[((size_t)(b * Nx)) * Hx + h];
    __syncthreads();
    float s = 0.f;
#pragma unroll 4
    for (int g = 0; g < 256; g++) s += dec[g] * Wmem[g * 256 + h];
    g_q[b * Hx + h] = s;
}

// ---- per-batch fused scores + softmax + context ----
__global__ __launch_bounds__(1024) void attn_k() {
    __shared__ float q[256];
    __shared__ float sc[1024];
    __shared__ float red[32];
    __shared__ float ctxp[4][256];
    __shared__ float stat[2];
    int b = blockIdx.x, tid = threadIdx.x;
    int warp = tid >> 5, lane = tid & 31;
    if (tid < 256) q[tid] = g_q[b * Hx + tid];
    __syncthreads();
    const float* hb = g_h + (size_t)b * Nx * Hx;
    for (int n = warp; n < Nx; n += 32) {
        const float* hr = hb + (size_t)n * Hx;
        float s = 0.f;
#pragma unroll
        for (int kk = 0; kk < 8; kk++) s += q[lane + kk * 32] * hr[lane + kk * 32];
#pragma unroll
        for (int o = 16; o; o >>= 1) s += __shfl_xor_sync(0xffffffffu, s, o);
        if (lane == 0) sc[n] = s;
    }
    __syncthreads();
    float sraw = (tid < Nx) ? sc[tid] : -3.4e38f;
    float v = sraw;
#pragma unroll
    for (int o = 16; o; o >>= 1) v = fmaxf(v, __shfl_xor_sync(0xffffffffu, v, o));
    if (lane == 0) red[warp] = v;
    __syncthreads();
    if (warp == 0) {
        float m = red[lane];
#pragma unroll
        for (int o = 16; o; o >>= 1) m = fmaxf(m, __shfl_xor_sync(0xffffffffu, m, o));
        if (lane == 0) stat[0] = m;
    }
    __syncthreads();
    float m = stat[0];
    float e = (tid < Nx) ? expf(sraw - m) : 0.f;
    sc[tid] = e;
    float s = e;
#pragma unroll
    for (int o = 16; o; o >>= 1) s += __shfl_xor_sync(0xffffffffu, s, o);
    if (lane == 0) red[warp] = s;
    __syncthreads();
    if (warp == 0) {
        float S = red[lane];
#pragma unroll
        for (int o = 16; o; o >>= 1) S += __shfl_xor_sync(0xffffffffu, S, o);
        if (lane == 0) stat[1] = S;
    }
    __syncthreads();
    float Sinv = 1.f / stat[1];
    int grp = tid >> 8, j = tid & 255;
    float p = 0.f;
    for (int n = grp; n < Nx; n += 4) p += sc[n] * hb[(size_t)n * Hx + j];
    ctxp[grp][j] = p;
    __syncthreads();
    if (tid < 256) {
        g_ctx[b * Hx + tid] =
            (ctxp[0][tid] + ctxp[1][tid] + ctxp[2][tid] + ctxp[3][tid]) * Sinv;
    }
}

// ---- head: hid = relu(ctx @ wh_W^T + wh_b); out = hid @ lin_W^T + lin_b ----
__global__ void final_k(const float* __restrict__ wh_W,
                        const float* __restrict__ wh_b,
                        const float* __restrict__ lin_W,
                        const float* __restrict__ lin_b,
                        float* __restrict__ out) {
    int b = blockIdx.x, tid = threadIdx.x;
    int warp = tid >> 5, lane = tid & 31;
    __shared__ float ctx[256];
    __shared__ float hid[256];
    ctx[tid] = g_ctx[b * Hx + tid];
    __syncthreads();
    for (int h = warp; h < 256; h += 8) {
        const float* wr = wh_W + (size_t)h * 256;
        float s = 0.f;
#pragma unroll
        for (int kk = 0; kk < 8; kk++) s += ctx[lane + kk * 32] * wr[lane + kk * 32];
#pragma unroll
        for (int o = 16; o; o >>= 1) s += __shfl_xor_sync(0xffffffffu, s, o);
        if (lane == 0) hid[h] = fmaxf(s + wh_b[h], 0.f);
    }
    __syncthreads();
    if (warp == 0) {
        for (int cc = 0; cc < Cx; cc++) {
            const float* lr = lin_W + (size_t)cc * 256;
            float s = 0.f;
#pragma unroll
            for (int kk = 0; kk < 8; kk++) s += hid[lane + kk * 32] * lr[lane + kk * 32];
#pragma unroll
            for (int o = 16; o; o >>= 1) s += __shfl_xor_sync(0xffffffffu, s, o);
            if (lane == 0) out[b * Cx + cc] = s + lin_b[cc];
        }
    }
}

extern "C" void kernel_launch(void* const* d_in, const int* in_sizes, int n_in,
                              void* d_out, int out_size) {
    const int* wordid   = (const int*)d_in[0];
    // d_in[1] = h0 (unused: every node is overwritten)
    const float* c0     = (const float*)d_in[2];
    const float* emb    = (const float*)d_in[3];
    const float* W_iou  = (const float*)d_in[4];
    const float* U_iou  = (const float*)d_in[5];
    const float* b_iou  = (const float*)d_in[6];
    const float* Uf_W   = (const float*)d_in[7];
    const float* Uf_b   = (const float*)d_in[8];
    const float* Wmem   = (const float*)d_in[9];
    const float* wh_W   = (const float*)d_in[10];
    const float* wh_b   = (const float*)d_in[11];
    const float* lin_W  = (const float*)d_in[12];
    const float* lin_b  = (const float*)d_in[13];
    float* out = (float*)d_out;
    (void)in_sizes; (void)n_in; (void)out_size;

    cudaFuncSetAttribute(hgemm_k<0>, cudaFuncAttributeMaxDynamicSharedMemorySize,
                         SMEM_GEMM);
    cudaFuncSetAttribute(hgemm_k<1>, cudaFuncAttributeMaxDynamicSharedMemorySize,
                         SMEM_GEMM);

    // fp16 mirrors
    emb16_k<<<(Vx * Xx + 255) / 256, 256>>>(emb);
    wiou16_k<<<(GH3 * Xx + 255) / 256, 256>>>(W_iou);
    wc16_k<<<(NC * K2H + 255) / 256, 256>>>(Uf_W, U_iou);

    // Leaves: iou = emb[wordid] @ W_iou^T  (M=65536, N=768, K=256)
    hgemm_k<0><<<dim3(Bx * NLEAF / 128, GH3 / 256), 256, SMEM_GEMM>>>(
        GH3, Xx, wordid, 0, 0);
    leaf_node_k<<<(Bx * NLEAF * Hx + 255) / 256, 256>>>(b_iou, c0);

    // Tree levels (serial)
    for (int level = 8; level >= 0; level--) {
        int npar = 1 << level, ps = npar - 1;
        hgemm_k<1><<<dim3(npar, NC / 256), 256, SMEM_GEMM>>>(
            NC, K2H, nullptr, ps, level);
        level_node_k<<<((Bx << level) * Hx + 255) / 256, 256>>>(
            b_iou, Uf_b, ps, level);
    }

    // Attention + head
    q_k<<<Bx, 256>>>(Wmem);
    attn_k<<<Bx, 1024>>>();
    final_k<<<Bx, 256>>>(wh_W, wh_b, lin_W, lin_b, out);
}

// round 7
// speedup vs baseline: 2.8826x; 1.0095x over previous
#include <cuda_runtime.h>
#include <cuda_fp16.h>
#include <math.h>
#include <stdint.h>

#define Bx 128
#define Nx 1023
#define Hx 256
#define Xx 256
#define Cx 10
#define Vx 32000
#define NLEAF 512
#define GH3 768      // 3*H
#define NC 1280      // 2H (f gates) + 3H (iou)
#define K2H 512      // 2*H

// ---- device-global scratch (no allocations allowed) ----
__device__ float g_h[(size_t)Bx * Nx * Hx];           // 134 MB (fp32, attention)
__device__ __half g_h16[(size_t)Bx * Nx * Hx];        // 67 MB (GEMM A operand)
__device__ float g_c[(size_t)Bx * Nx * Hx];           // 134 MB
__device__ float g_scr[(size_t)Bx * NLEAF * GH3];     // 201 MB (per-level reuse)
__device__ __half g_emb16[(size_t)Vx * Xx];           // 16 MB
__device__ __half g_Wc16[NC * K2H];                   // packed [Uf_W ; U_iou] fp16
__device__ __half g_Wiou16[GH3 * Xx];
__device__ float g_q[Bx * Hx];
__device__ float g_ctx[Bx * Hx];

__device__ __forceinline__ float sigm(float x) { return 1.f / (1.f + expf(-x)); }

#define LDSM4(r0, r1, r2, r3, addr)                                          \
    asm volatile("ldmatrix.sync.aligned.m8n8.x4.shared.b16 {%0,%1,%2,%3}, [%4];" \
                 : "=r"(r0), "=r"(r1), "=r"(r2), "=r"(r3) : "r"(addr))

#define HMMA(d, a, b0, b1)                                                   \
    asm volatile(                                                            \
        "mma.sync.aligned.m16n8k16.row.col.f32.f16.f16.f32 "                 \
        "{%0,%1,%2,%3}, {%4,%5,%6,%7}, {%8,%9}, {%0,%1,%2,%3};"              \
        : "+f"(d[0]), "+f"(d[1]), "+f"(d[2]), "+f"(d[3])                     \
        : "r"(a[0]), "r"(a[1]), "r"(a[2]), "r"(a[3]), "r"(b0), "r"(b1))

#define CP16(dst, src)                                                       \
    asm volatile("cp.async.cg.shared.global [%0], [%1], 16;" ::"r"(dst),     \
                 "l"(src))
#define CPCOMMIT() asm volatile("cp.async.commit_group;")
#define CPWAIT(n) asm volatile("cp.async.wait_group %0;" ::"n"(n))

__device__ __forceinline__ uint32_t smem_u32(const void* p) {
    uint32_t a;
    asm("{ .reg .u64 t; cvta.to.shared.u64 t, %1; cvt.u32.u64 %0, t; }"
        : "=r"(a) : "l"(p));
    return a;
}

// ---- fp16 mirror setup ----
__global__ void emb16_k(const float* __restrict__ emb) {
    int i = blockIdx.x * 256 + threadIdx.x;
    if (i < Vx * Xx) g_emb16[i] = __float2half(emb[i]);
}
__global__ void wiou16_k(const float* __restrict__ W_iou) {
    int i = blockIdx.x * 256 + threadIdx.x;
    if (i < GH3 * Xx) g_Wiou16[i] = __float2half(W_iou[i]);
}
__global__ void wc16_k(const float* __restrict__ Uf_W,
                       const float* __restrict__ U_iou) {
    int i = blockIdx.x * 256 + threadIdx.x;
    if (i >= NC * K2H) return;
    float v = (i < K2H * K2H) ? Uf_W[i] : U_iou[i - K2H * K2H];
    g_Wc16[i] = __float2half(v);
}

// ===================================================================
// FP16 tensor GEMM: block 128x256, 8 warps (2M x 4N), warp tile 64x64.
// K-chunk 32, 5-stage cp.async ring (wait(3) -> sync -> copy ci+4 ->
// compute ci): ~3 chunks (~770cyc) of overlap hides GMEM latency.
// out[r][n] = sum_k A[r][k] * Wt[n][k]  -> g_scr (fp32)
// MODE 0: A row r=(b*512+l) -> g_emb16[wordid[b,511+l]]  (K=256, Wt=g_Wiou16)
// MODE 1: A row r=(b*npar+pl) -> g_h16[b, 2*(ps+pl)+1]   (K=512, Wt=g_Wc16)
// ===================================================================
#define ROWB 80
#define ABYTES (128 * ROWB)                 // 10240
#define STAGEB ((128 + 256) * ROWB)         // 30720 per stage
#define NSTAGE 5
#define SMEM_GEMM (NSTAGE * STAGEB)         // 153600

template <int MODE>
__global__ __launch_bounds__(256, 1) void hgemm_k(
    int Ncols, int K, const int* __restrict__ wordid, int ps, int shift) {
    extern __shared__ char smem[];
    const uint32_t sb = smem_u32(smem);
    const int tid = threadIdx.x, lane = tid & 31, warp = tid >> 5;
    const int rowStart = blockIdx.x * 128, colStart = blockIdx.y * 256;
    const int warpM = warp >> 2, warpN = warp & 3;

    // staging: A row tid>>1 (16-half slice), B row tid (32 halves)
    const int sr = tid >> 1, kh = (tid & 1) * 16;
    const __half* ap;
    {
        int r = rowStart + sr;
        if (MODE == 0) {
            int b = r >> 9, l = r & 511;
            int w = wordid[b * Nx + (NLEAF - 1) + l];
            ap = g_emb16 + (size_t)w * Xx + kh;
        } else {
            int b = r >> shift, pl = r & ((1 << shift) - 1);
            ap = g_h16 + ((size_t)(b * Nx + 2 * (ps + pl) + 1)) * Hx + kh;
        }
    }
    const __half* bp =
        (MODE == 0 ? (const __half*)g_Wiou16 : (const __half*)g_Wc16) +
        (size_t)(colStart + tid) * K;
    const uint32_t adst0 = sb + sr * ROWB + kh * 2;
    const uint32_t bdst0 = sb + ABYTES + tid * ROWB;

    // ldmatrix bases (stage 0; add slot*STAGEB)
    const int aRow = warpM * 64 + (lane & 7) + ((lane >> 3) & 1) * 8;
    const int aK = (lane >> 4) * 8;
    const int bRow = warpN * 64 + (lane & 7) + ((lane >> 4) & 1) * 8;
    const int bK = ((lane >> 3) & 1) * 8;
    const uint32_t aA0 = sb + aRow * ROWB + aK * 2;
    const uint32_t bA0 = sb + ABYTES + bRow * ROWB + bK * 2;

    float acc[4][8][4];
#pragma unroll
    for (int mi = 0; mi < 4; mi++)
#pragma unroll
        for (int ni = 0; ni < 8; ni++)
#pragma unroll
            for (int cc = 0; cc < 4; cc++) acc[mi][ni][cc] = 0.f;

    const int nch = K / 32;

    // prologue: stage chunks 0..3 into slots 0..3
#pragma unroll
    for (int s = 0; s < 4; s++) {
        const uint32_t ad = adst0 + s * STAGEB;
        const uint32_t bd = bdst0 + s * STAGEB;
        const __half* ag = ap + s * 32;
        const __half* bg = bp + s * 32;
        CP16(ad, ag); CP16(ad + 16, ag + 8);
        CP16(bd, bg); CP16(bd + 16, bg + 8);
        CP16(bd + 32, bg + 16); CP16(bd + 48, bg + 24);
        CPCOMMIT();
    }

    int slot = 0, pslot = 4;
    for (int ci = 0; ci < nch; ci++) {
        const int ahead = nch - 1 - ci;
        if (ahead >= 3) { CPWAIT(3); }
        else if (ahead == 2) { CPWAIT(2); }
        else if (ahead == 1) { CPWAIT(1); }
        else { CPWAIT(0); }
        __syncthreads();
        if (ci + 4 < nch) {
            const uint32_t ad = adst0 + pslot * STAGEB;
            const uint32_t bd = bdst0 + pslot * STAGEB;
            const __half* ag = ap + (ci + 4) * 32;
            const __half* bg = bp + (ci + 4) * 32;
            CP16(ad, ag); CP16(ad + 16, ag + 8);
            CP16(bd, bg); CP16(bd + 16, bg + 8);
            CP16(bd + 32, bg + 16); CP16(bd + 48, bg + 24);
            CPCOMMIT();
            pslot = (pslot + 1 == NSTAGE) ? 0 : pslot + 1;
        }
        const uint32_t ab = aA0 + slot * STAGEB;
        const uint32_t bb = bA0 + slot * STAGEB;
#pragma unroll
        for (int ks = 0; ks < 2; ks++) {
            uint32_t a[4][4], b[4][4];
#pragma unroll
            for (int mi = 0; mi < 4; mi++)
                LDSM4(a[mi][0], a[mi][1], a[mi][2], a[mi][3],
                      ab + mi * (16 * ROWB) + ks * 32);
#pragma unroll
            for (int nt = 0; nt < 4; nt++)
                LDSM4(b[nt][0], b[nt][1], b[nt][2], b[nt][3],
                      bb + nt * (16 * ROWB) + ks * 32);
#pragma unroll
            for (int mi = 0; mi < 4; mi++)
#pragma unroll
                for (int ni = 0; ni < 8; ni++)
                    HMMA(acc[mi][ni], a[mi], b[ni >> 1][(ni & 1) * 2],
                         b[ni >> 1][(ni & 1) * 2 + 1]);
        }
        slot = (slot + 1 == NSTAGE) ? 0 : slot + 1;
    }

    const int g = lane >> 2, tt = lane & 3;
#pragma unroll
    for (int mi = 0; mi < 4; mi++)
#pragma unroll
        for (int ni = 0; ni < 8; ni++) {
            int row = rowStart + warpM * 64 + mi * 16 + g;
            int colb = colStart + warpN * 64 + ni * 8 + tt * 2;
            *(float2*)(g_scr + (size_t)row * Ncols + colb) =
                make_float2(acc[mi][ni][0], acc[mi][ni][1]);
            *(float2*)(g_scr + (size_t)(row + 8) * Ncols + colb) =
                make_float2(acc[mi][ni][2], acc[mi][ni][3]);
        }
}

// ---- leaf epilogue: iou -> (h, c) at nodes 511..1022 ----
__global__ void leaf_node_k(const float* __restrict__ b_iou,
                            const float* __restrict__ c0) {
    int i = blockIdx.x * 256 + threadIdx.x;
    if (i >= Bx * NLEAF * Hx) return;
    int j = i & 255;
    int rl = i >> 8;              // b*512 + l
    int b = rl >> 9, l = rl & 511;
    const float* row = g_scr + (size_t)rl * GH3;
    float iv = row[j] + b_iou[j];
    float ov = row[256 + j] + b_iou[256 + j];
    float uv = row[512 + j] + b_iou[512 + j];
    size_t idx = ((size_t)(b * Nx + (NLEAF - 1) + l)) * Hx + j;
    float c = sigm(iv) * tanhf(uv) + c0[idx];
    float h = sigm(ov) * tanhf(c);
    g_c[idx] = c;
    g_h[idx] = h;
    g_h16[idx] = __float2half(h);
}

// ---- level epilogue: [f1,f2,iou] + child c -> parent (h, c) ----
__global__ void level_node_k(const float* __restrict__ b_iou,
                             const float* __restrict__ Uf_b, int ps, int shift) {
    int total = (Bx << shift) * Hx;
    int i = blockIdx.x * 256 + threadIdx.x;
    if (i >= total) return;
    int j = i & 255;
    int rl = i >> 8;                       // b*npar + pl
    int b = rl >> shift, pl = rl & ((1 << shift) - 1);
    const float* row = g_scr + (size_t)rl * NC;
    int p = ps + pl;
    size_t ci1 = ((size_t)(b * Nx + 2 * p + 1)) * Hx + j;
    float f1 = sigm(row[j] + Uf_b[j]);
    float f2 = sigm(row[256 + j] + Uf_b[256 + j]);
    float csum = f1 * g_c[ci1] + f2 * g_c[ci1 + Hx];
    float iv = row[512 + j] + b_iou[j];
    float ov = row[768 + j] + b_iou[256 + j];
    float uv = row[1024 + j] + b_iou[512 + j];
    float c = sigm(iv) * tanhf(uv) + csum;
    float h = sigm(ov) * tanhf(c);
    size_t pi = ((size_t)(b * Nx + p)) * Hx + j;
    g_c[pi] = c;
    g_h[pi] = h;
    g_h16[pi] = __float2half(h);
}

// ---- q[b] = Wmem^T @ h[b,0,:]  (scores factored: dec^T Wmem h = q . h) ----
__global__ void q_k(const float* __restrict__ Wmem) {
    int b = blockIdx.x, h = threadIdx.x;
    __shared__ float dec[256];
    dec[h] = g_h[((size_t)(b * Nx)) * Hx + h];
    __syncthreads();
    float s = 0.f;
#pragma unroll 4
    for (int g = 0; g < 256; g++) s += dec[g] * Wmem[g * 256 + h];
    g_q[b * Hx + h] = s;
}

// ---- per-batch fused scores + softmax + context ----
__global__ __launch_bounds__(1024) void attn_k() {
    __shared__ float q[256];
    __shared__ float sc[1024];
    __shared__ float red[32];
    __shared__ float ctxp[4][256];
    __shared__ float stat[2];
    int b = blockIdx.x, tid = threadIdx.x;
    int warp = tid >> 5, lane = tid & 31;
    if (tid < 256) q[tid] = g_q[b * Hx + tid];
    __syncthreads();
    const float* hb = g_h + (size_t)b * Nx * Hx;
    for (int n = warp; n < Nx; n += 32) {
        const float* hr = hb + (size_t)n * Hx;
        float s = 0.f;
#pragma unroll
        for (int kk = 0; kk < 8; kk++) s += q[lane + kk * 32] * hr[lane + kk * 32];
#pragma unroll
        for (int o = 16; o; o >>= 1) s += __shfl_xor_sync(0xffffffffu, s, o);
        if (lane == 0) sc[n] = s;
    }
    __syncthreads();
    float sraw = (tid < Nx) ? sc[tid] : -3.4e38f;
    float v = sraw;
#pragma unroll
    for (int o = 16; o; o >>= 1) v = fmaxf(v, __shfl_xor_sync(0xffffffffu, v, o));
    if (lane == 0) red[warp] = v;
    __syncthreads();
    if (warp == 0) {
        float m = red[lane];
#pragma unroll
        for (int o = 16; o; o >>= 1) m = fmaxf(m, __shfl_xor_sync(0xffffffffu, m, o));
        if (lane == 0) stat[0] = m;
    }
    __syncthreads();
    float m = stat[0];
    float e = (tid < Nx) ? expf(sraw - m) : 0.f;
    sc[tid] = e;
    float s = e;
#pragma unroll
    for (int o = 16; o; o >>= 1) s += __shfl_xor_sync(0xffffffffu, s, o);
    if (lane == 0) red[warp] = s;
    __syncthreads();
    if (warp == 0) {
        float S = red[lane];
#pragma unroll
        for (int o = 16; o; o >>= 1) S += __shfl_xor_sync(0xffffffffu, S, o);
        if (lane == 0) stat[1] = S;
    }
    __syncthreads();
    float Sinv = 1.f / stat[1];
    int grp = tid >> 8, j = tid & 255;
    float p = 0.f;
    for (int n = grp; n < Nx; n += 4) p += sc[n] * hb[(size_t)n * Hx + j];
    ctxp[grp][j] = p;
    __syncthreads();
    if (tid < 256) {
        g_ctx[b * Hx + tid] =
            (ctxp[0][tid] + ctxp[1][tid] + ctxp[2][tid] + ctxp[3][tid]) * Sinv;
    }
}

// ---- head: hid = relu(ctx @ wh_W^T + wh_b); out = hid @ lin_W^T + lin_b ----
__global__ void final_k(const float* __restrict__ wh_W,
                        const float* __restrict__ wh_b,
                        const float* __restrict__ lin_W,
                        const float* __restrict__ lin_b,
                        float* __restrict__ out) {
    int b = blockIdx.x, tid = threadIdx.x;
    int warp = tid >> 5, lane = tid & 31;
    __shared__ float ctx[256];
    __shared__ float hid[256];
    ctx[tid] = g_ctx[b * Hx + tid];
    __syncthreads();
    for (int h = warp; h < 256; h += 8) {
        const float* wr = wh_W + (size_t)h * 256;
        float s = 0.f;
#pragma unroll
        for (int kk = 0; kk < 8; kk++) s += ctx[lane + kk * 32] * wr[lane + kk * 32];
#pragma unroll
        for (int o = 16; o; o >>= 1) s += __shfl_xor_sync(0xffffffffu, s, o);
        if (lane == 0) hid[h] = fmaxf(s + wh_b[h], 0.f);
    }
    __syncthreads();
    if (warp == 0) {
        for (int cc = 0; cc < Cx; cc++) {
            const float* lr = lin_W + (size_t)cc * 256;
            float s = 0.f;
#pragma unroll
            for (int kk = 0; kk < 8; kk++) s += hid[lane + kk * 32] * lr[lane + kk * 32];
#pragma unroll
            for (int o = 16; o; o >>= 1) s += __shfl_xor_sync(0xffffffffu, s, o);
            if (lane == 0) out[b * Cx + cc] = s + lin_b[cc];
        }
    }
}

extern "C" void kernel_launch(void* const* d_in, const int* in_sizes, int n_in,
                              void* d_out, int out_size) {
    const int* wordid   = (const int*)d_in[0];
    // d_in[1] = h0 (unused: every node is overwritten)
    const float* c0     = (const float*)d_in[2];
    const float* emb    = (const float*)d_in[3];
    const float* W_iou  = (const float*)d_in[4];
    const float* U_iou  = (const float*)d_in[5];
    const float* b_iou  = (const float*)d_in[6];
    const float* Uf_W   = (const float*)d_in[7];
    const float* Uf_b   = (const float*)d_in[8];
    const float* Wmem   = (const float*)d_in[9];
    const float* wh_W   = (const float*)d_in[10];
    const float* wh_b   = (const float*)d_in[11];
    const float* lin_W  = (const float*)d_in[12];
    const float* lin_b  = (const float*)d_in[13];
    float* out = (float*)d_out;
    (void)in_sizes; (void)n_in; (void)out_size;

    cudaFuncSetAttribute(hgemm_k<0>, cudaFuncAttributeMaxDynamicSharedMemorySize,
                         SMEM_GEMM);
    cudaFuncSetAttribute(hgemm_k<1>, cudaFuncAttributeMaxDynamicSharedMemorySize,
                         SMEM_GEMM);

    // fp16 mirrors
    emb16_k<<<(Vx * Xx + 255) / 256, 256>>>(emb);
    wiou16_k<<<(GH3 * Xx + 255) / 256, 256>>>(W_iou);
    wc16_k<<<(NC * K2H + 255) / 256, 256>>>(Uf_W, U_iou);

    // Leaves: iou = emb[wordid] @ W_iou^T  (M=65536, N=768, K=256)
    hgemm_k<0><<<dim3(Bx * NLEAF / 128, GH3 / 256), 256, SMEM_GEMM>>>(
        GH3, Xx, wordid, 0, 0);
    leaf_node_k<<<(Bx * NLEAF * Hx + 255) / 256, 256>>>(b_iou, c0);

    // Tree levels (serial)
    for (int level = 8; level >= 0; level--) {
        int npar = 1 << level, ps = npar - 1;
        hgemm_k<1><<<dim3(npar, NC / 256), 256, SMEM_GEMM>>>(
            NC, K2H, nullptr, ps, level);
        level_node_k<<<((Bx << level) * Hx + 255) / 256, 256>>>(
            b_iou, Uf_b, ps, level);
    }

    // Attention + head
    q_k<<<Bx, 256>>>(Wmem);
    attn_k<<<Bx, 1024>>>();
    final_k<<<Bx, 256>>>(wh_W, wh_b, lin_W, lin_b, out);
}

// round 8
// speedup vs baseline: 2.9540x; 1.0248x over previous
#include <cuda_runtime.h>
#include <cuda_fp16.h>
#include <math.h>
#include <stdint.h>

#define Bx 128
#define Nx 1023
#define Hx 256
#define Xx 256
#define Cx 10
#define Vx 32000
#define NLEAF 512
#define GH3 768      // 3*H
#define NC 1280      // 2H (f gates) + 3H (iou)
#define K2H 512      // 2*H

// ---- device-global scratch (no allocations allowed) ----
__device__ float g_h[(size_t)Bx * Nx * Hx];           // 134 MB (fp32, attention)
__device__ __half g_h16[(size_t)Bx * Nx * Hx];        // 67 MB (GEMM A operand)
__device__ float g_c[(size_t)Bx * Nx * Hx];           // 134 MB
__device__ float g_scr[(size_t)Bx * NLEAF * GH3];     // 201 MB (per-level reuse)
__device__ __half g_emb16[(size_t)Vx * Xx];           // 16 MB
__device__ __half g_Wc16[NC * K2H];                   // packed [Uf_W ; U_iou] fp16
__device__ __half g_Wiou16[GH3 * Xx];
__device__ float g_q[Bx * Hx];
__device__ float g_ctx[Bx * Hx];

__device__ __forceinline__ float sigm(float x) { return 1.f / (1.f + expf(-x)); }

#define LDSM4(r0, r1, r2, r3, addr)                                          \
    asm volatile("ldmatrix.sync.aligned.m8n8.x4.shared.b16 {%0,%1,%2,%3}, [%4];" \
                 : "=r"(r0), "=r"(r1), "=r"(r2), "=r"(r3) : "r"(addr))

#define HMMA(d, a, b0, b1)                                                   \
    asm volatile(                                                            \
        "mma.sync.aligned.m16n8k16.row.col.f32.f16.f16.f32 "                 \
        "{%0,%1,%2,%3}, {%4,%5,%6,%7}, {%8,%9}, {%0,%1,%2,%3};"              \
        : "+f"(d[0]), "+f"(d[1]), "+f"(d[2]), "+f"(d[3])                     \
        : "r"(a[0]), "r"(a[1]), "r"(a[2]), "r"(a[3]), "r"(b0), "r"(b1))

#define CP16(dst, src)                                                       \
    asm volatile("cp.async.cg.shared.global [%0], [%1], 16;" ::"r"(dst),     \
                 "l"(src))
#define CPCOMMIT() asm volatile("cp.async.commit_group;")
#define CPWAIT(n) asm volatile("cp.async.wait_group %0;" ::"n"(n))

__device__ __forceinline__ uint32_t smem_u32(const void* p) {
    uint32_t a;
    asm("{ .reg .u64 t; cvta.to.shared.u64 t, %1; cvt.u32.u64 %0, t; }"
        : "=r"(a) : "l"(p));
    return a;
}

// ---- fp16 mirror setup ----
__global__ void emb16_k(const float* __restrict__ emb) {
    int i = blockIdx.x * 256 + threadIdx.x;
    if (i < Vx * Xx) g_emb16[i] = __float2half(emb[i]);
}
__global__ void wiou16_k(const float* __restrict__ W_iou) {
    int i = blockIdx.x * 256 + threadIdx.x;
    if (i < GH3 * Xx) g_Wiou16[i] = __float2half(W_iou[i]);
}
__global__ void wc16_k(const float* __restrict__ Uf_W,
                       const float* __restrict__ U_iou) {
    int i = blockIdx.x * 256 + threadIdx.x;
    if (i >= NC * K2H) return;
    float v = (i < K2H * K2H) ? Uf_W[i] : U_iou[i - K2H * K2H];
    g_Wc16[i] = __float2half(v);
}

// ===================================================================
// FP16 tensor GEMM: block 128x256, 8 warps (2M x 4N), warp tile 64x64.
// K-chunk 32, 5-stage cp.async ring + PING-PONG REGISTER FRAGMENTS:
// per chunk: cp.async(ci+4) -> LDSM frags(ks1) -> HMMA ks0 ->
// wait+sync -> LDSM frags(ci+1,ks0) -> HMMA ks1. Tensor pipe always
// has a ready fragment set; LDSM latency hides under the other ks.
// MODE 0: A row r=(b*512+l) -> g_emb16[wordid[b,511+l]]  (K=256, Wt=g_Wiou16)
// MODE 1: A row r=(b*npar+pl) -> g_h16[b, 2*(ps+pl)+1]   (K=512, Wt=g_Wc16)
// ===================================================================
#define ROWB 80
#define ABYTES (128 * ROWB)                 // 10240
#define STAGEB ((128 + 256) * ROWB)         // 30720 per stage
#define NSTAGE 5
#define SMEM_GEMM (NSTAGE * STAGEB)         // 153600

template <int MODE>
__global__ __launch_bounds__(256, 1) void hgemm_k(
    int Ncols, int K, const int* __restrict__ wordid, int ps, int shift) {
    extern __shared__ char smem[];
    const uint32_t sb = smem_u32(smem);
    const int tid = threadIdx.x, lane = tid & 31, warp = tid >> 5;
    const int rowStart = blockIdx.x * 128, colStart = blockIdx.y * 256;
    const int warpM = warp >> 2, warpN = warp & 3;

    // staging: A row tid>>1 (16-half slice), B row tid (32 halves)
    const int sr = tid >> 1, kh = (tid & 1) * 16;
    const __half* ap;
    {
        int r = rowStart + sr;
        if (MODE == 0) {
            int b = r >> 9, l = r & 511;
            int w = wordid[b * Nx + (NLEAF - 1) + l];
            ap = g_emb16 + (size_t)w * Xx + kh;
        } else {
            int b = r >> shift, pl = r & ((1 << shift) - 1);
            ap = g_h16 + ((size_t)(b * Nx + 2 * (ps + pl) + 1)) * Hx + kh;
        }
    }
    const __half* bp =
        (MODE == 0 ? (const __half*)g_Wiou16 : (const __half*)g_Wc16) +
        (size_t)(colStart + tid) * K;
    const uint32_t adst0 = sb + sr * ROWB + kh * 2;
    const uint32_t bdst0 = sb + ABYTES + tid * ROWB;

    // ldmatrix bases (stage 0; add slot*STAGEB)
    const int aRow = warpM * 64 + (lane & 7) + ((lane >> 3) & 1) * 8;
    const int aK = (lane >> 4) * 8;
    const int bRow = warpN * 64 + (lane & 7) + ((lane >> 4) & 1) * 8;
    const int bK = ((lane >> 3) & 1) * 8;
    const uint32_t aA0 = sb + aRow * ROWB + aK * 2;
    const uint32_t bA0 = sb + ABYTES + bRow * ROWB + bK * 2;

    float acc[4][8][4];
#pragma unroll
    for (int mi = 0; mi < 4; mi++)
#pragma unroll
        for (int ni = 0; ni < 8; ni++)
#pragma unroll
            for (int cc = 0; cc < 4; cc++) acc[mi][ni][cc] = 0.f;

    const int nch = K / 32;

    // prologue: stage chunks 0..3 into slots 0..3
#pragma unroll
    for (int s = 0; s < 4; s++) {
        const uint32_t ad = adst0 + s * STAGEB;
        const uint32_t bd = bdst0 + s * STAGEB;
        const __half* ag = ap + s * 32;
        const __half* bg = bp + s * 32;
        CP16(ad, ag); CP16(ad + 16, ag + 8);
        CP16(bd, bg); CP16(bd + 16, bg + 8);
        CP16(bd + 32, bg + 16); CP16(bd + 48, bg + 24);
        CPCOMMIT();
    }

    // ping-pong register fragments
    uint32_t aF[2][4][4], bF[2][4][4];

    CPWAIT(3);
    __syncthreads();
    // preload fragments for (chunk 0, ks 0) into set 0
#pragma unroll
    for (int mi = 0; mi < 4; mi++)
        LDSM4(aF[0][mi][0], aF[0][mi][1], aF[0][mi][2], aF[0][mi][3],
              aA0 + mi * (16 * ROWB));
#pragma unroll
    for (int nt = 0; nt < 4; nt++)
        LDSM4(bF[0][nt][0], bF[0][nt][1], bF[0][nt][2], bF[0][nt][3],
              bA0 + nt * (16 * ROWB));

    int slot = 0, pslot = 4;
    for (int ci = 0; ci < nch; ci++) {
        // 1. issue cp.async for chunk ci+4 (into slot freed before our
        //    preceding sync)
        if (ci + 4 < nch) {
            const uint32_t ad = adst0 + pslot * STAGEB;
            const uint32_t bd = bdst0 + pslot * STAGEB;
            const __half* ag = ap + (ci + 4) * 32;
            const __half* bg = bp + (ci + 4) * 32;
            CP16(ad, ag); CP16(ad + 16, ag + 8);
            CP16(bd, bg); CP16(bd + 16, bg + 8);
            CP16(bd + 32, bg + 16); CP16(bd + 48, bg + 24);
            CPCOMMIT();
            pslot = (pslot + 1 == NSTAGE) ? 0 : pslot + 1;
        }
        const uint32_t ab = aA0 + slot * STAGEB;
        const uint32_t bb = bA0 + slot * STAGEB;
        // 2. load fragments for ks1 into set 1 (overlaps with step 3)
#pragma unroll
        for (int mi = 0; mi < 4; mi++)
            LDSM4(aF[1][mi][0], aF[1][mi][1], aF[1][mi][2], aF[1][mi][3],
                  ab + mi * (16 * ROWB) + 32);
#pragma unroll
        for (int nt = 0; nt < 4; nt++)
            LDSM4(bF[1][nt][0], bF[1][nt][1], bF[1][nt][2], bF[1][nt][3],
                  bb + nt * (16 * ROWB) + 32);
        // 3. compute ks0 with set 0
#pragma unroll
        for (int mi = 0; mi < 4; mi++)
#pragma unroll
            for (int ni = 0; ni < 8; ni++)
                HMMA(acc[mi][ni], aF[0][mi], bF[0][ni >> 1][(ni & 1) * 2],
                     bF[0][ni >> 1][(ni & 1) * 2 + 1]);
        // 4. wait for chunk ci+1, sync (also frees slot for next cp.async)
        if (ci + 1 < nch) {
            const int last = (ci + 4 < nch) ? (ci + 4) : (nch - 1);
            const int ahead = last - (ci + 1);
            if (ahead >= 3) { CPWAIT(3); }
            else if (ahead == 2) { CPWAIT(2); }
            else if (ahead == 1) { CPWAIT(1); }
            else { CPWAIT(0); }
            __syncthreads();
            const int slotn = (slot + 1 == NSTAGE) ? 0 : slot + 1;
            const uint32_t ab2 = aA0 + slotn * STAGEB;
            const uint32_t bb2 = bA0 + slotn * STAGEB;
            // 5. load fragments (ci+1, ks0) into set 0 (overlaps step 6)
#pragma unroll
            for (int mi = 0; mi < 4; mi++)
                LDSM4(aF[0][mi][0], aF[0][mi][1], aF[0][mi][2], aF[0][mi][3],
                      ab2 + mi * (16 * ROWB));
#pragma unroll
            for (int nt = 0; nt < 4; nt++)
                LDSM4(bF[0][nt][0], bF[0][nt][1], bF[0][nt][2], bF[0][nt][3],
                      bb2 + nt * (16 * ROWB));
            slot = slotn;
        }
        // 6. compute ks1 with set 1
#pragma unroll
        for (int mi = 0; mi < 4; mi++)
#pragma unroll
            for (int ni = 0; ni < 8; ni++)
                HMMA(acc[mi][ni], aF[1][mi], bF[1][ni >> 1][(ni & 1) * 2],
                     bF[1][ni >> 1][(ni & 1) * 2 + 1]);
    }

    const int g = lane >> 2, tt = lane & 3;
#pragma unroll
    for (int mi = 0; mi < 4; mi++)
#pragma unroll
        for (int ni = 0; ni < 8; ni++) {
            int row = rowStart + warpM * 64 + mi * 16 + g;
            int colb = colStart + warpN * 64 + ni * 8 + tt * 2;
            *(float2*)(g_scr + (size_t)row * Ncols + colb) =
                make_float2(acc[mi][ni][0], acc[mi][ni][1]);
            *(float2*)(g_scr + (size_t)(row + 8) * Ncols + colb) =
                make_float2(acc[mi][ni][2], acc[mi][ni][3]);
        }
}

// ---- leaf epilogue: iou -> (h, c) at nodes 511..1022 ----
__global__ void leaf_node_k(const float* __restrict__ b_iou,
                            const float* __restrict__ c0) {
    int i = blockIdx.x * 256 + threadIdx.x;
    if (i >= Bx * NLEAF * Hx) return;
    int j = i & 255;
    int rl = i >> 8;              // b*512 + l
    int b = rl >> 9, l = rl & 511;
    const float* row = g_scr + (size_t)rl * GH3;
    float iv = row[j] + b_iou[j];
    float ov = row[256 + j] + b_iou[256 + j];
    float uv = row[512 + j] + b_iou[512 + j];
    size_t idx = ((size_t)(b * Nx + (NLEAF - 1) + l)) * Hx + j;
    float c = sigm(iv) * tanhf(uv) + c0[idx];
    float h = sigm(ov) * tanhf(c);
    g_c[idx] = c;
    g_h[idx] = h;
    g_h16[idx] = __float2half(h);
}

// ---- level epilogue: [f1,f2,iou] + child c -> parent (h, c) ----
__global__ void level_node_k(const float* __restrict__ b_iou,
                             const float* __restrict__ Uf_b, int ps, int shift) {
    int total = (Bx << shift) * Hx;
    int i = blockIdx.x * 256 + threadIdx.x;
    if (i >= total) return;
    int j = i & 255;
    int rl = i >> 8;                       // b*npar + pl
    int b = rl >> shift, pl = rl & ((1 << shift) - 1);
    const float* row = g_scr + (size_t)rl * NC;
    int p = ps + pl;
    size_t ci1 = ((size_t)(b * Nx + 2 * p + 1)) * Hx + j;
    float f1 = sigm(row[j] + Uf_b[j]);
    float f2 = sigm(row[256 + j] + Uf_b[256 + j]);
    float csum = f1 * g_c[ci1] + f2 * g_c[ci1 + Hx];
    float iv = row[512 + j] + b_iou[j];
    float ov = row[768 + j] + b_iou[256 + j];
    float uv = row[1024 + j] + b_iou[512 + j];
    float c = sigm(iv) * tanhf(uv) + csum;
    float h = sigm(ov) * tanhf(c);
    size_t pi = ((size_t)(b * Nx + p)) * Hx + j;
    g_c[pi] = c;
    g_h[pi] = h;
    g_h16[pi] = __float2half(h);
}

// ---- q[b] = Wmem^T @ h[b,0,:]  (scores factored: dec^T Wmem h = q . h) ----
__global__ void q_k(const float* __restrict__ Wmem) {
    int b = blockIdx.x, h = threadIdx.x;
    __shared__ float dec[256];
    dec[h] = g_h[((size_t)(b * Nx)) * Hx + h];
    __syncthreads();
    float s = 0.f;
#pragma unroll 4
    for (int g = 0; g < 256; g++) s += dec[g] * Wmem[g * 256 + h];
    g_q[b * Hx + h] = s;
}

// ---- per-batch fused scores + softmax + context ----
__global__ __launch_bounds__(1024) void attn_k() {
    __shared__ float q[256];
    __shared__ float sc[1024];
    __shared__ float red[32];
    __shared__ float ctxp[4][256];
    __shared__ float stat[2];
    int b = blockIdx.x, tid = threadIdx.x;
    int warp = tid >> 5, lane = tid & 31;
    if (tid < 256) q[tid] = g_q[b * Hx + tid];
    __syncthreads();
    const float* hb = g_h + (size_t)b * Nx * Hx;
    for (int n = warp; n < Nx; n += 32) {
        const float* hr = hb + (size_t)n * Hx;
        float s = 0.f;
#pragma unroll
        for (int kk = 0; kk < 8; kk++) s += q[lane + kk * 32] * hr[lane + kk * 32];
#pragma unroll
        for (int o = 16; o; o >>= 1) s += __shfl_xor_sync(0xffffffffu, s, o);
        if (lane == 0) sc[n] = s;
    }
    __syncthreads();
    float sraw = (tid < Nx) ? sc[tid] : -3.4e38f;
    float v = sraw;
#pragma unroll
    for (int o = 16; o; o >>= 1) v = fmaxf(v, __shfl_xor_sync(0xffffffffu, v, o));
    if (lane == 0) red[warp] = v;
    __syncthreads();
    if (warp == 0) {
        float m = red[lane];
#pragma unroll
        for (int o = 16; o; o >>= 1) m = fmaxf(m, __shfl_xor_sync(0xffffffffu, m, o));
        if (lane == 0) stat[0] = m;
    }
    __syncthreads();
    float m = stat[0];
    float e = (tid < Nx) ? expf(sraw - m) : 0.f;
    sc[tid] = e;
    float s = e;
#pragma unroll
    for (int o = 16; o; o >>= 1) s += __shfl_xor_sync(0xffffffffu, s, o);
    if (lane == 0) red[warp] = s;
    __syncthreads();
    if (warp == 0) {
        float S = red[lane];
#pragma unroll
        for (int o = 16; o; o >>= 1) S += __shfl_xor_sync(0xffffffffu, S, o);
        if (lane == 0) stat[1] = S;
    }
    __syncthreads();
    float Sinv = 1.f / stat[1];
    int grp = tid >> 8, j = tid & 255;
    float p = 0.f;
    for (int n = grp; n < Nx; n += 4) p += sc[n] * hb[(size_t)n * Hx + j];
    ctxp[grp][j] = p;
    __syncthreads();
    if (tid < 256) {
        g_ctx[b * Hx + tid] =
            (ctxp[0][tid] + ctxp[1][tid] + ctxp[2][tid] + ctxp[3][tid]) * Sinv;
    }
}

// ---- head: hid = relu(ctx @ wh_W^T + wh_b); out = hid @ lin_W^T + lin_b ----
__global__ void final_k(const float* __restrict__ wh_W,
                        const float* __restrict__ wh_b,
                        const float* __restrict__ lin_W,
                        const float* __restrict__ lin_b,
                        float* __restrict__ out) {
    int b = blockIdx.x, tid = threadIdx.x;
    int warp = tid >> 5, lane = tid & 31;
    __shared__ float ctx[256];
    __shared__ float hid[256];
    ctx[tid] = g_ctx[b * Hx + tid];
    __syncthreads();
    for (int h = warp; h < 256; h += 8) {
        const float* wr = wh_W + (size_t)h * 256;
        float s = 0.f;
#pragma unroll
        for (int kk = 0; kk < 8; kk++) s += ctx[lane + kk * 32] * wr[lane + kk * 32];
#pragma unroll
        for (int o = 16; o; o >>= 1) s += __shfl_xor_sync(0xffffffffu, s, o);
        if (lane == 0) hid[h] = fmaxf(s + wh_b[h], 0.f);
    }
    __syncthreads();
    if (warp == 0) {
        for (int cc = 0; cc < Cx; cc++) {
            const float* lr = lin_W + (size_t)cc * 256;
            float s = 0.f;
#pragma unroll
            for (int kk = 0; kk < 8; kk++) s += hid[lane + kk * 32] * lr[lane + kk * 32];
#pragma unroll
            for (int o = 16; o; o >>= 1) s += __shfl_xor_sync(0xffffffffu, s, o);
            if (lane == 0) out[b * Cx + cc] = s + lin_b[cc];
        }
    }
}

extern "C" void kernel_launch(void* const* d_in, const int* in_sizes, int n_in,
                              void* d_out, int out_size) {
    const int* wordid   = (const int*)d_in[0];
    // d_in[1] = h0 (unused: every node is overwritten)
    const float* c0     = (const float*)d_in[2];
    const float* emb    = (const float*)d_in[3];
    const float* W_iou  = (const float*)d_in[4];
    const float* U_iou  = (const float*)d_in[5];
    const float* b_iou  = (const float*)d_in[6];
    const float* Uf_W   = (const float*)d_in[7];
    const float* Uf_b   = (const float*)d_in[8];
    const float* Wmem   = (const float*)d_in[9];
    const float* wh_W   = (const float*)d_in[10];
    const float* wh_b   = (const float*)d_in[11];
    const float* lin_W  = (const float*)d_in[12];
    const float* lin_b  = (const float*)d_in[13];
    float* out = (float*)d_out;
    (void)in_sizes; (void)n_in; (void)out_size;

    cudaFuncSetAttribute(hgemm_k<0>, cudaFuncAttributeMaxDynamicSharedMemorySize,
                         SMEM_GEMM);
    cudaFuncSetAttribute(hgemm_k<1>, cudaFuncAttributeMaxDynamicSharedMemorySize,
                         SMEM_GEMM);

    // fp16 mirrors
    emb16_k<<<(Vx * Xx + 255) / 256, 256>>>(emb);
    wiou16_k<<<(GH3 * Xx + 255) / 256, 256>>>(W_iou);
    wc16_k<<<(NC * K2H + 255) / 256, 256>>>(Uf_W, U_iou);

    // Leaves: iou = emb[wordid] @ W_iou^T  (M=65536, N=768, K=256)
    hgemm_k<0><<<dim3(Bx * NLEAF / 128, GH3 / 256), 256, SMEM_GEMM>>>(
        GH3, Xx, wordid, 0, 0);
    leaf_node_k<<<(Bx * NLEAF * Hx + 255) / 256, 256>>>(b_iou, c0);

    // Tree levels (serial)
    for (int level = 8; level >= 0; level--) {
        int npar = 1 << level, ps = npar - 1;
        hgemm_k<1><<<dim3(npar, NC / 256), 256, SMEM_GEMM>>>(
            NC, K2H, nullptr, ps, level);
        level_node_k<<<((Bx << level) * Hx + 255) / 256, 256>>>(
            b_iou, Uf_b, ps, level);
    }

    // Attention + head
    q_k<<<Bx, 256>>>(Wmem);
    attn_k<<<Bx, 1024>>>();
    final_k<<<Bx, 256>>>(wh_W, wh_b, lin_W, lin_b, out);
}

// round 9
// speedup vs baseline: 3.0550x; 1.0342x over previous
#include <cuda_runtime.h>
#include <cuda_fp16.h>
#include <math.h>
#include <stdint.h>

#define Bx 128
#define Nx 1023
#define Hx 256
#define Xx 256
#define Cx 10
#define Vx 32000
#define NLEAF 512
#define GH3 768      // 3*H
#define NC 1280      // 2H (f gates) + 3H (iou)
#define K2H 512      // 2*H

// ---- device-global scratch (no allocations allowed) ----
__device__ float g_h[(size_t)Bx * Nx * Hx];           // fp32 h (attention)
__device__ __half g_h16[(size_t)Bx * Nx * Hx];        // fp16 h (GEMM A)
__device__ float g_c[(size_t)Bx * Nx * Hx];           // fp32 c
__device__ __half g_emb16[(size_t)Vx * Xx];
__device__ __half g_Wc16[NC * K2H];     // gate-interleaved [f1,f2,i,o,u]x8 groups
__device__ __half g_Wiou16[GH3 * Xx];   // gate-interleaved [i,o,u]x8 groups
__device__ float g_q[Bx * Hx];
__device__ float g_ctx[Bx * Hx];

__device__ __forceinline__ float sigm(float x) { return 1.f / (1.f + expf(-x)); }

#define LDSM4(r0, r1, r2, r3, addr)                                          \
    asm volatile("ldmatrix.sync.aligned.m8n8.x4.shared.b16 {%0,%1,%2,%3}, [%4];" \
                 : "=r"(r0), "=r"(r1), "=r"(r2), "=r"(r3) : "r"(addr))
#define LDSM2(r0, r1, addr)                                                  \
    asm volatile("ldmatrix.sync.aligned.m8n8.x2.shared.b16 {%0,%1}, [%2];"   \
                 : "=r"(r0), "=r"(r1) : "r"(addr))

#define HMMA(d, a, b0, b1)                                                   \
    asm volatile(                                                            \
        "mma.sync.aligned.m16n8k16.row.col.f32.f16.f16.f32 "                 \
        "{%0,%1,%2,%3}, {%4,%5,%6,%7}, {%8,%9}, {%0,%1,%2,%3};"              \
        : "+f"(d[0]), "+f"(d[1]), "+f"(d[2]), "+f"(d[3])                     \
        : "r"(a[0]), "r"(a[1]), "r"(a[2]), "r"(a[3]), "r"(b0), "r"(b1))

#define CP16(dst, src)                                                       \
    asm volatile("cp.async.cg.shared.global [%0], [%1], 16;" ::"r"(dst),     \
                 "l"(src))
#define CPCOMMIT() asm volatile("cp.async.commit_group;")
#define CPWAIT(n) asm volatile("cp.async.wait_group %0;" ::"n"(n))

__device__ __forceinline__ uint32_t smem_u32(const void* p) {
    uint32_t a;
    asm("{ .reg .u64 t; cvta.to.shared.u64 t, %1; cvt.u32.u64 %0, t; }"
        : "=r"(a) : "l"(p));
    return a;
}

// ---- fp16 mirror setup (with gate interleave) ----
__global__ void emb16_k(const float* __restrict__ emb) {
    int i = blockIdx.x * 256 + threadIdx.x;
    if (i < Vx * Xx) g_emb16[i] = __float2half(emb[i]);
}
// leaf weights: permuted row r -> group r/24, gate (r%24)/8, unit (r/24)*8+(r%8)
__global__ void wiou16_k(const float* __restrict__ W_iou) {
    int i = blockIdx.x * 256 + threadIdx.x;
    if (i >= GH3 * Xx) return;
    int r = i >> 8, k = i & 255;
    int w = r % 24, gate = w >> 3, j = (r / 24) * 8 + (w & 7);
    g_Wiou16[i] = __float2half(W_iou[(gate * 256 + j) * Xx + k]);
}
// level weights: permuted row r -> group r/40, gate (r%40)/8 in [f1,f2,i,o,u]
__global__ void wc16_k(const float* __restrict__ Uf_W,
                       const float* __restrict__ U_iou) {
    int i = blockIdx.x * 256 + threadIdx.x;
    if (i >= NC * K2H) return;
    int r = i >> 9, k = i & 511;
    int w = r % 40, gate = w >> 3, j = (r / 40) * 8 + (w & 7);
    float v = (gate < 2) ? Uf_W[(gate * 256 + j) * K2H + k]
                         : U_iou[((gate - 2) * 256 + j) * K2H + k];
    g_Wc16[i] = __float2half(v);
}

// ===================================================================
// Fused FP16 tensor GEMM + TreeLSTM node epilogue.
// Block 128 x NBLK, 8 warps (2M x 4N). 5-stage cp.async ring +
// ping-pong register fragments (structure identical to R8 kernel).
// Gate-interleaved weights => each thread owns ALL gates for its
// (row, unit) pairs -> epilogue computes c/h in-register, writes
// g_c/g_h/g_h16 directly. No scratch, no separate node kernels.
// MODE 0 (leaf):  NBLK=192, warp N=48 = 2 groups of [i,o,u]x8. K=256.
// MODE 1 (level): NBLK=160, warp N=40 = 1 group of [f1,f2,i,o,u]x8. K=512.
// ===================================================================
#define ROWB 80
#define ABYTES (128 * ROWB)
#define NSTAGE 5

template <int MODE>
__global__ __launch_bounds__(256, 1) void hgemm_k(
    const int* __restrict__ wordid, const float* __restrict__ c0,
    const float* __restrict__ b_iou, const float* __restrict__ Uf_b,
    int K, int ps, int shift) {
    constexpr int NBLK = MODE ? 160 : 192;
    constexpr int NI = MODE ? 5 : 6;       // n8 tiles per warp
    constexpr int WN = MODE ? 40 : 48;     // warp N width
    constexpr int STAGEB = (128 + NBLK) * ROWB;
    extern __shared__ char smem[];
    const uint32_t sb = smem_u32(smem);
    const int tid = threadIdx.x, lane = tid & 31, warp = tid >> 5;
    const int rowStart = blockIdx.x * 128, colStart = blockIdx.y * NBLK;
    const int warpM = warp >> 2, warpN = warp & 3;

    // --- staging pointers: A row tid>>1 (16-half slice), B row tid ---
    const int sr = tid >> 1, kh = (tid & 1) * 16;
    const __half* ap;
    {
        int r = rowStart + sr;
        if (MODE == 0) {
            int b = r >> 9, l = r & 511;
            int w = wordid[b * Nx + (NLEAF - 1) + l];
            ap = g_emb16 + (size_t)w * Xx + kh;
        } else {
            int b = r >> shift, pl = r & ((1 << shift) - 1);
            ap = g_h16 + ((size_t)(b * Nx + 2 * (ps + pl) + 1)) * Hx + kh;
        }
    }
    const int bcol = colStart + (tid < NBLK ? tid : 0);
    const __half* bp =
        (MODE == 0 ? (const __half*)g_Wiou16 : (const __half*)g_Wc16) +
        (size_t)bcol * K;
    const uint32_t adst0 = sb + sr * ROWB + kh * 2;
    const uint32_t bdst0 = sb + ABYTES + (tid < NBLK ? tid : 0) * ROWB;
    const bool doB = (tid < NBLK);

    // --- ldmatrix bases ---
    const int aRow = warpM * 64 + (lane & 7) + ((lane >> 3) & 1) * 8;
    const int aK = (lane >> 4) * 8;
    const int bRow = warpN * WN + (lane & 7) + ((lane >> 4) & 1) * 8;
    const int bK = ((lane >> 3) & 1) * 8;
    const uint32_t aA0 = sb + aRow * ROWB + aK * 2;
    const uint32_t bA0 = sb + ABYTES + bRow * ROWB + bK * 2;
    const int l15 = lane & 15;
    const uint32_t b2A0 =
        sb + ABYTES + (warpN * WN + 32 + (l15 & 7)) * ROWB + (l15 >> 3) * 16;

    float acc[4][NI][4];
#pragma unroll
    for (int mi = 0; mi < 4; mi++)
#pragma unroll
        for (int ni = 0; ni < NI; ni++)
#pragma unroll
            for (int cc = 0; cc < 4; cc++) acc[mi][ni][cc] = 0.f;

    const int nch = K / 32;

    // prologue: stage chunks 0..3
#pragma unroll
    for (int s = 0; s < 4; s++) {
        const uint32_t ad = adst0 + s * STAGEB;
        const __half* ag = ap + s * 32;
        CP16(ad, ag); CP16(ad + 16, ag + 8);
        if (doB) {
            const uint32_t bd = bdst0 + s * STAGEB;
            const __half* bg = bp + s * 32;
            CP16(bd, bg); CP16(bd + 16, bg + 8);
            CP16(bd + 32, bg + 16); CP16(bd + 48, bg + 24);
        }
        CPCOMMIT();
    }

    uint32_t aF[2][4][4], bq[2][2 * NI];

    CPWAIT(3);
    __syncthreads();
    // preload set 0: (chunk 0, ks 0)
#pragma unroll
    for (int mi = 0; mi < 4; mi++)
        LDSM4(aF[0][mi][0], aF[0][mi][1], aF[0][mi][2], aF[0][mi][3],
              aA0 + mi * (16 * ROWB));
    if (MODE == 0) {
        LDSM4(bq[0][0], bq[0][1], bq[0][2], bq[0][3], bA0);
        LDSM4(bq[0][4], bq[0][5], bq[0][6], bq[0][7], bA0 + 16 * ROWB);
        LDSM4(bq[0][8], bq[0][9], bq[0][10], bq[0][11], bA0 + 32 * ROWB);
    } else {
        LDSM4(bq[0][0], bq[0][1], bq[0][2], bq[0][3], bA0);
        LDSM4(bq[0][4], bq[0][5], bq[0][6], bq[0][7], bA0 + 16 * ROWB);
        LDSM2(bq[0][8], bq[0][9], b2A0);
    }

    int slot = 0, pslot = 4;
    for (int ci = 0; ci < nch; ci++) {
        if (ci + 4 < nch) {
            const uint32_t ad = adst0 + pslot * STAGEB;
            const __half* ag = ap + (ci + 4) * 32;
            CP16(ad, ag); CP16(ad + 16, ag + 8);
            if (doB) {
                const uint32_t bd = bdst0 + pslot * STAGEB;
                const __half* bg = bp + (ci + 4) * 32;
                CP16(bd, bg); CP16(bd + 16, bg + 8);
                CP16(bd + 32, bg + 16); CP16(bd + 48, bg + 24);
            }
            CPCOMMIT();
            pslot = (pslot + 1 == NSTAGE) ? 0 : pslot + 1;
        }
        const uint32_t ab = aA0 + slot * STAGEB;
        const uint32_t bb = bA0 + slot * STAGEB;
        const uint32_t bb2 = b2A0 + slot * STAGEB;
        // load set 1 = (ci, ks1)
#pragma unroll
        for (int mi = 0; mi < 4; mi++)
            LDSM4(aF[1][mi][0], aF[1][mi][1], aF[1][mi][2], aF[1][mi][3],
                  ab + mi * (16 * ROWB) + 32);
        if (MODE == 0) {
            LDSM4(bq[1][0], bq[1][1], bq[1][2], bq[1][3], bb + 32);
            LDSM4(bq[1][4], bq[1][5], bq[1][6], bq[1][7], bb + 16 * ROWB + 32);
            LDSM4(bq[1][8], bq[1][9], bq[1][10], bq[1][11], bb + 32 * ROWB + 32);
        } else {
            LDSM4(bq[1][0], bq[1][1], bq[1][2], bq[1][3], bb + 32);
            LDSM4(bq[1][4], bq[1][5], bq[1][6], bq[1][7], bb + 16 * ROWB + 32);
            LDSM2(bq[1][8], bq[1][9], bb2 + 32);
        }
        // compute ks0 with set 0
#pragma unroll
        for (int mi = 0; mi < 4; mi++)
#pragma unroll
            for (int ni = 0; ni < NI; ni++)
                HMMA(acc[mi][ni], aF[0][mi], bq[0][2 * ni], bq[0][2 * ni + 1]);
        // wait chunk ci+1, sync, load set 0 = (ci+1, ks0)
        if (ci + 1 < nch) {
            const int last = (ci + 4 < nch) ? (ci + 4) : (nch - 1);
            const int ahead = last - (ci + 1);
            if (ahead >= 3) { CPWAIT(3); }
            else if (ahead == 2) { CPWAIT(2); }
            else if (ahead == 1) { CPWAIT(1); }
            else { CPWAIT(0); }
            __syncthreads();
            const int slotn = (slot + 1 == NSTAGE) ? 0 : slot + 1;
            const uint32_t ab2 = aA0 + slotn * STAGEB;
            const uint32_t bbn = bA0 + slotn * STAGEB;
            const uint32_t bb2n = b2A0 + slotn * STAGEB;
#pragma unroll
            for (int mi = 0; mi < 4; mi++)
                LDSM4(aF[0][mi][0], aF[0][mi][1], aF[0][mi][2], aF[0][mi][3],
                      ab2 + mi * (16 * ROWB));
            if (MODE == 0) {
                LDSM4(bq[0][0], bq[0][1], bq[0][2], bq[0][3], bbn);
                LDSM4(bq[0][4], bq[0][5], bq[0][6], bq[0][7], bbn + 16 * ROWB);
                LDSM4(bq[0][8], bq[0][9], bq[0][10], bq[0][11], bbn + 32 * ROWB);
            } else {
                LDSM4(bq[0][0], bq[0][1], bq[0][2], bq[0][3], bbn);
                LDSM4(bq[0][4], bq[0][5], bq[0][6], bq[0][7], bbn + 16 * ROWB);
                LDSM2(bq[0][8], bq[0][9], b2A0 + slotn * STAGEB);
            }
            slot = slotn;
            (void)bb2n;
        }
        // compute ks1 with set 1
#pragma unroll
        for (int mi = 0; mi < 4; mi++)
#pragma unroll
            for (int ni = 0; ni < NI; ni++)
                HMMA(acc[mi][ni], aF[1][mi], bq[1][2 * ni], bq[1][2 * ni + 1]);
    }

    // ================= fused node epilogue =================
    const int g = lane >> 2, tt = lane & 3;
    if (MODE == 0) {
        // warp N=48 = 2 groups of [i,o,u] x 8 units
#pragma unroll
        for (int grp = 0; grp < 2; grp++) {
            const int jb = ((colStart + warpN * 48 + grp * 24) / 24) * 8 + tt * 2;
            const float bi0 = b_iou[jb], bi1 = b_iou[jb + 1];
            const float bo0 = b_iou[256 + jb], bo1 = b_iou[257 + jb];
            const float bu0 = b_iou[512 + jb], bu1 = b_iou[513 + jb];
#pragma unroll
            for (int mi = 0; mi < 4; mi++) {
#pragma unroll
                for (int hf = 0; hf < 2; hf++) {
                    const int r = rowStart + warpM * 64 + mi * 16 + g + hf * 8;
                    const int b = r >> 9, l = r & 511;
                    const size_t idx =
                        ((size_t)(b * Nx + (NLEAF - 1) + l)) * Hx + jb;
                    const float iv0 = acc[mi][grp * 3 + 0][hf * 2 + 0] + bi0;
                    const float iv1 = acc[mi][grp * 3 + 0][hf * 2 + 1] + bi1;
                    const float ov0 = acc[mi][grp * 3 + 1][hf * 2 + 0] + bo0;
                    const float ov1 = acc[mi][grp * 3 + 1][hf * 2 + 1] + bo1;
                    const float uv0 = acc[mi][grp * 3 + 2][hf * 2 + 0] + bu0;
                    const float uv1 = acc[mi][grp * 3 + 2][hf * 2 + 1] + bu1;
                    const float2 cz = *(const float2*)(c0 + idx);
                    const float cA = sigm(iv0) * tanhf(uv0) + cz.x;
                    const float cB = sigm(iv1) * tanhf(uv1) + cz.y;
                    const float hA = sigm(ov0) * tanhf(cA);
                    const float hB = sigm(ov1) * tanhf(cB);
                    *(float2*)(g_c + idx) = make_float2(cA, cB);
                    *(float2*)(g_h + idx) = make_float2(hA, hB);
                    *(__half2*)(g_h16 + idx) = __floats2half2_rn(hA, hB);
                }
            }
        }
    } else {
        // warp N=40 = 1 group of [f1,f2,i,o,u] x 8 units
        const int jb = ((colStart + warpN * 40) / 40) * 8 + tt * 2;
        const float bf10 = Uf_b[jb], bf11 = Uf_b[jb + 1];
        const float bf20 = Uf_b[256 + jb], bf21 = Uf_b[257 + jb];
        const float bi0 = b_iou[jb], bi1 = b_iou[jb + 1];
        const float bo0 = b_iou[256 + jb], bo1 = b_iou[257 + jb];
        const float bu0 = b_iou[512 + jb], bu1 = b_iou[513 + jb];
        const int mask = (1 << shift) - 1;
#pragma unroll
        for (int mi = 0; mi < 4; mi++) {
#pragma unroll
            for (int hf = 0; hf < 2; hf++) {
                const int r = rowStart + warpM * 64 + mi * 16 + g + hf * 8;
                const int b = r >> shift, pl = r & mask;
                const int p = ps + pl;
                const size_t cidx = ((size_t)(b * Nx + 2 * p + 1)) * Hx + jb;
                const float2 c1 = *(const float2*)(g_c + cidx);
                const float2 c2 = *(const float2*)(g_c + cidx + Hx);
                const float f10 = sigm(acc[mi][0][hf * 2 + 0] + bf10);
                const float f11 = sigm(acc[mi][0][hf * 2 + 1] + bf11);
                const float f20 = sigm(acc[mi][1][hf * 2 + 0] + bf20);
                const float f21 = sigm(acc[mi][1][hf * 2 + 1] + bf21);
                const float cs0 = f10 * c1.x + f20 * c2.x;
                const float cs1 = f11 * c1.y + f21 * c2.y;
                const float iv0 = acc[mi][2][hf * 2 + 0] + bi0;
                const float iv1 = acc[mi][2][hf * 2 + 1] + bi1;
                const float ov0 = acc[mi][3][hf * 2 + 0] + bo0;
                const float ov1 = acc[mi][3][hf * 2 + 1] + bo1;
                const float uv0 = acc[mi][4][hf * 2 + 0] + bu0;
                const float uv1 = acc[mi][4][hf * 2 + 1] + bu1;
                const float cA = sigm(iv0) * tanhf(uv0) + cs0;
                const float cB = sigm(iv1) * tanhf(uv1) + cs1;
                const float hA = sigm(ov0) * tanhf(cA);
                const float hB = sigm(ov1) * tanhf(cB);
                const size_t pidx = ((size_t)(b * Nx + p)) * Hx + jb;
                *(float2*)(g_c + pidx) = make_float2(cA, cB);
                *(float2*)(g_h + pidx) = make_float2(hA, hB);
                *(__half2*)(g_h16 + pidx) = __floats2half2_rn(hA, hB);
            }
        }
    }
}

// ---- q[b] = Wmem^T @ h[b,0,:]  (scores factored: dec^T Wmem h = q . h) ----
__global__ void q_k(const float* __restrict__ Wmem) {
    int b = blockIdx.x, h = threadIdx.x;
    __shared__ float dec[256];
    dec[h] = g_h[((size_t)(b * Nx)) * Hx + h];
    __syncthreads();
    float s = 0.f;
#pragma unroll 4
    for (int g = 0; g < 256; g++) s += dec[g] * Wmem[g * 256 + h];
    g_q[b * Hx + h] = s;
}

// ---- per-batch fused scores + softmax + context ----
__global__ __launch_bounds__(1024) void attn_k() {
    __shared__ float q[256];
    __shared__ float sc[1024];
    __shared__ float red[32];
    __shared__ float ctxp[4][256];
    __shared__ float stat[2];
    int b = blockIdx.x, tid = threadIdx.x;
    int warp = tid >> 5, lane = tid & 31;
    if (tid < 256) q[tid] = g_q[b * Hx + tid];
    __syncthreads();
    const float* hb = g_h + (size_t)b * Nx * Hx;
    for (int n = warp; n < Nx; n += 32) {
        const float* hr = hb + (size_t)n * Hx;
        float s = 0.f;
#pragma unroll
        for (int kk = 0; kk < 8; kk++) s += q[lane + kk * 32] * hr[lane + kk * 32];
#pragma unroll
        for (int o = 16; o; o >>= 1) s += __shfl_xor_sync(0xffffffffu, s, o);
        if (lane == 0) sc[n] = s;
    }
    __syncthreads();
    float sraw = (tid < Nx) ? sc[tid] : -3.4e38f;
    float v = sraw;
#pragma unroll
    for (int o = 16; o; o >>= 1) v = fmaxf(v, __shfl_xor_sync(0xffffffffu, v, o));
    if (lane == 0) red[warp] = v;
    __syncthreads();
    if (warp == 0) {
        float m = red[lane];
#pragma unroll
        for (int o = 16; o; o >>= 1) m = fmaxf(m, __shfl_xor_sync(0xffffffffu, m, o));
        if (lane == 0) stat[0] = m;
    }
    __syncthreads();
    float m = stat[0];
    float e = (tid < Nx) ? expf(sraw - m) : 0.f;
    sc[tid] = e;
    float s = e;
#pragma unroll
    for (int o = 16; o; o >>= 1) s += __shfl_xor_sync(0xffffffffu, s, o);
    if (lane == 0) red[warp] = s;
    __syncthreads();
    if (warp == 0) {
        float S = red[lane];
#pragma unroll
        for (int o = 16; o; o >>= 1) S += __shfl_xor_sync(0xffffffffu, S, o);
        if (lane == 0) stat[1] = S;
    }
    __syncthreads();
    float Sinv = 1.f / stat[1];
    int grp = tid >> 8, j = tid & 255;
    float p = 0.f;
    for (int n = grp; n < Nx; n += 4) p += sc[n] * hb[(size_t)n * Hx + j];
    ctxp[grp][j] = p;
    __syncthreads();
    if (tid < 256) {
        g_ctx[b * Hx + tid] =
            (ctxp[0][tid] + ctxp[1][tid] + ctxp[2][tid] + ctxp[3][tid]) * Sinv;
    }
}

// ---- head: hid = relu(ctx @ wh_W^T + wh_b); out = hid @ lin_W^T + lin_b ----
__global__ void final_k(const float* __restrict__ wh_W,
                        const float* __restrict__ wh_b,
                        const float* __restrict__ lin_W,
                        const float* __restrict__ lin_b,
                        float* __restrict__ out) {
    int b = blockIdx.x, tid = threadIdx.x;
    int warp = tid >> 5, lane = tid & 31;
    __shared__ float ctx[256];
    __shared__ float hid[256];
    ctx[tid] = g_ctx[b * Hx + tid];
    __syncthreads();
    for (int h = warp; h < 256; h += 8) {
        const float* wr = wh_W + (size_t)h * 256;
        float s = 0.f;
#pragma unroll
        for (int kk = 0; kk < 8; kk++) s += ctx[lane + kk * 32] * wr[lane + kk * 32];
#pragma unroll
        for (int o = 16; o; o >>= 1) s += __shfl_xor_sync(0xffffffffu, s, o);
        if (lane == 0) hid[h] = fmaxf(s + wh_b[h], 0.f);
    }
    __syncthreads();
    if (warp == 0) {
        for (int cc = 0; cc < Cx; cc++) {
            const float* lr = lin_W + (size_t)cc * 256;
            float s = 0.f;
#pragma unroll
            for (int kk = 0; kk < 8; kk++) s += hid[lane + kk * 32] * lr[lane + kk * 32];
#pragma unroll
            for (int o = 16; o; o >>= 1) s += __shfl_xor_sync(0xffffffffu, s, o);
            if (lane == 0) out[b * Cx + cc] = s + lin_b[cc];
        }
    }
}

extern "C" void kernel_launch(void* const* d_in, const int* in_sizes, int n_in,
                              void* d_out, int out_size) {
    const int* wordid   = (const int*)d_in[0];
    // d_in[1] = h0 (unused: every node is overwritten)
    const float* c0     = (const float*)d_in[2];
    const float* emb    = (const float*)d_in[3];
    const float* W_iou  = (const float*)d_in[4];
    const float* U_iou  = (const float*)d_in[5];
    const float* b_iou  = (const float*)d_in[6];
    const float* Uf_W   = (const float*)d_in[7];
    const float* Uf_b   = (const float*)d_in[8];
    const float* Wmem   = (const float*)d_in[9];
    const float* wh_W   = (const float*)d_in[10];
    const float* wh_b   = (const float*)d_in[11];
    const float* lin_W  = (const float*)d_in[12];
    const float* lin_b  = (const float*)d_in[13];
    float* out = (float*)d_out;
    (void)in_sizes; (void)n_in; (void)out_size;

    const int SMEM0 = NSTAGE * (128 + 192) * ROWB;   // 128000
    const int SMEM1 = NSTAGE * (128 + 160) * ROWB;   // 115200
    cudaFuncSetAttribute(hgemm_k<0>, cudaFuncAttributeMaxDynamicSharedMemorySize,
                         SMEM0);
    cudaFuncSetAttribute(hgemm_k<1>, cudaFuncAttributeMaxDynamicSharedMemorySize,
                         SMEM1);

    // fp16 mirrors (gate-interleaved weights)
    emb16_k<<<(Vx * Xx + 255) / 256, 256>>>(emb);
    wiou16_k<<<(GH3 * Xx + 255) / 256, 256>>>(W_iou);
    wc16_k<<<(NC * K2H + 255) / 256, 256>>>(Uf_W, U_iou);

    // Leaves fused: GEMM + node -> h/c at nodes 511..1022
    hgemm_k<0><<<dim3(Bx * NLEAF / 128, GH3 / 192), 256, SMEM0>>>(
        wordid, c0, b_iou, Uf_b, Xx, 0, 0);

    // Tree levels (serial), fused GEMM + node per level
    for (int level = 8; level >= 0; level--) {
        int npar = 1 << level, ps = npar - 1;
        hgemm_k<1><<<dim3(npar, NC / 160), 256, SMEM1>>>(
            nullptr, nullptr, b_iou, Uf_b, K2H, ps, level);
    }

    // Attention + head
    q_k<<<Bx, 256>>>(Wmem);
    attn_k<<<Bx, 1024>>>();
    final_k<<<Bx, 256>>>(wh_W, wh_b, lin_W, lin_b, out);
}

// round 10
// speedup vs baseline: 3.5039x; 1.1470x over previous
#include <cuda_runtime.h>
#include <cuda_fp16.h>
#include <math.h>
#include <stdint.h>

#define Bx 128
#define Nx 1023
#define Hx 256
#define Xx 256
#define Cx 10
#define Vx 32000
#define NLEAF 512
#define GH3 768      // 3*H
#define NC 1280      // 2H (f gates) + 3H (iou)
#define K2H 512      // 2*H

// ---- device-global scratch (no allocations allowed) ----
__device__ float g_h[(size_t)Bx * Nx * Hx];           // fp32 h (attention)
__device__ __half g_h16[(size_t)Bx * Nx * Hx];        // fp16 h (GEMM A)
__device__ float g_c[(size_t)Bx * Nx * Hx];           // fp32 c
__device__ __half g_emb16[(size_t)Vx * Xx];
__device__ __half g_Wc16[NC * K2H];     // gate-interleaved [f1,f2,i,o,u]x8 groups
__device__ __half g_Wiou16[GH3 * Xx];   // gate-interleaved [i,o,u]x8 groups
__device__ float g_q[Bx * Hx];
__device__ float g_ctx[Bx * Hx];

// fast transcendentals: MUFU-based, rel err ~1e-6 (budget is 1e-3; current 3e-4)
__device__ __forceinline__ float sigm(float x) {
    return __fdividef(1.f, 1.f + __expf(-x));
}
__device__ __forceinline__ float ftanh(float x) {
    x = fminf(fmaxf(x, -15.f), 15.f);     // avoid inf/inf; tanh(15)==1 in fp32
    float e = __expf(2.f * x);
    return __fdividef(e - 1.f, e + 1.f);
}

#define LDSM4(r0, r1, r2, r3, addr)                                          \
    asm volatile("ldmatrix.sync.aligned.m8n8.x4.shared.b16 {%0,%1,%2,%3}, [%4];" \
                 : "=r"(r0), "=r"(r1), "=r"(r2), "=r"(r3) : "r"(addr))
#define LDSM2(r0, r1, addr)                                                  \
    asm volatile("ldmatrix.sync.aligned.m8n8.x2.shared.b16 {%0,%1}, [%2];"   \
                 : "=r"(r0), "=r"(r1) : "r"(addr))

#define HMMA(d, a, b0, b1)                                                   \
    asm volatile(                                                            \
        "mma.sync.aligned.m16n8k16.row.col.f32.f16.f16.f32 "                 \
        "{%0,%1,%2,%3}, {%4,%5,%6,%7}, {%8,%9}, {%0,%1,%2,%3};"              \
        : "+f"(d[0]), "+f"(d[1]), "+f"(d[2]), "+f"(d[3])                     \
        : "r"(a[0]), "r"(a[1]), "r"(a[2]), "r"(a[3]), "r"(b0), "r"(b1))

#define CP16(dst, src)                                                       \
    asm volatile("cp.async.cg.shared.global [%0], [%1], 16;" ::"r"(dst),     \
                 "l"(src))
#define CPCOMMIT() asm volatile("cp.async.commit_group;")
#define CPWAIT(n) asm volatile("cp.async.wait_group %0;" ::"n"(n))

__device__ __forceinline__ uint32_t smem_u32(const void* p) {
    uint32_t a;
    asm("{ .reg .u64 t; cvta.to.shared.u64 t, %1; cvt.u32.u64 %0, t; }"
        : "=r"(a) : "l"(p));
    return a;
}

// ---- fp16 mirror setup (with gate interleave) ----
__global__ void emb16_k(const float* __restrict__ emb) {
    int i = blockIdx.x * 256 + threadIdx.x;
    if (i < Vx * Xx) g_emb16[i] = __float2half(emb[i]);
}
// leaf weights: permuted row r -> group r/24, gate (r%24)/8, unit (r/24)*8+(r%8)
__global__ void wiou16_k(const float* __restrict__ W_iou) {
    int i = blockIdx.x * 256 + threadIdx.x;
    if (i >= GH3 * Xx) return;
    int r = i >> 8, k = i & 255;
    int w = r % 24, gate = w >> 3, j = (r / 24) * 8 + (w & 7);
    g_Wiou16[i] = __float2half(W_iou[(gate * 256 + j) * Xx + k]);
}
// level weights: permuted row r -> group r/40, gate (r%40)/8 in [f1,f2,i,o,u]
__global__ void wc16_k(const float* __restrict__ Uf_W,
                       const float* __restrict__ U_iou) {
    int i = blockIdx.x * 256 + threadIdx.x;
    if (i >= NC * K2H) return;
    int r = i >> 9, k = i & 511;
    int w = r % 40, gate = w >> 3, j = (r / 40) * 8 + (w & 7);
    float v = (gate < 2) ? Uf_W[(gate * 256 + j) * K2H + k]
                         : U_iou[((gate - 2) * 256 + j) * K2H + k];
    g_Wc16[i] = __float2half(v);
}

// ===================================================================
// Fused FP16 tensor GEMM + TreeLSTM node epilogue (structure = R9,
// epilogue transcendentals now MUFU-based fast math).
// MODE 0 (leaf):  NBLK=192, warp N=48 = 2 groups of [i,o,u]x8. K=256.
// MODE 1 (level): NBLK=160, warp N=40 = 1 group of [f1,f2,i,o,u]x8. K=512.
// ===================================================================
#define ROWB 80
#define ABYTES (128 * ROWB)
#define NSTAGE 5

template <int MODE>
__global__ __launch_bounds__(256, 1) void hgemm_k(
    const int* __restrict__ wordid, const float* __restrict__ c0,
    const float* __restrict__ b_iou, const float* __restrict__ Uf_b,
    int K, int ps, int shift) {
    constexpr int NBLK = MODE ? 160 : 192;
    constexpr int NI = MODE ? 5 : 6;       // n8 tiles per warp
    constexpr int WN = MODE ? 40 : 48;     // warp N width
    constexpr int STAGEB = (128 + NBLK) * ROWB;
    extern __shared__ char smem[];
    const uint32_t sb = smem_u32(smem);
    const int tid = threadIdx.x, lane = tid & 31, warp = tid >> 5;
    const int rowStart = blockIdx.x * 128, colStart = blockIdx.y * NBLK;
    const int warpM = warp >> 2, warpN = warp & 3;

    // --- staging pointers: A row tid>>1 (16-half slice), B row tid ---
    const int sr = tid >> 1, kh = (tid & 1) * 16;
    const __half* ap;
    {
        int r = rowStart + sr;
        if (MODE == 0) {
            int b = r >> 9, l = r & 511;
            int w = wordid[b * Nx + (NLEAF - 1) + l];
            ap = g_emb16 + (size_t)w * Xx + kh;
        } else {
            int b = r >> shift, pl = r & ((1 << shift) - 1);
            ap = g_h16 + ((size_t)(b * Nx + 2 * (ps + pl) + 1)) * Hx + kh;
        }
    }
    const int bcol = colStart + (tid < NBLK ? tid : 0);
    const __half* bp =
        (MODE == 0 ? (const __half*)g_Wiou16 : (const __half*)g_Wc16) +
        (size_t)bcol * K;
    const uint32_t adst0 = sb + sr * ROWB + kh * 2;
    const uint32_t bdst0 = sb + ABYTES + (tid < NBLK ? tid : 0) * ROWB;
    const bool doB = (tid < NBLK);

    // --- ldmatrix bases ---
    const int aRow = warpM * 64 + (lane & 7) + ((lane >> 3) & 1) * 8;
    const int aK = (lane >> 4) * 8;
    const int bRow = warpN * WN + (lane & 7) + ((lane >> 4) & 1) * 8;
    const int bK = ((lane >> 3) & 1) * 8;
    const uint32_t aA0 = sb + aRow * ROWB + aK * 2;
    const uint32_t bA0 = sb + ABYTES + bRow * ROWB + bK * 2;
    const int l15 = lane & 15;
    const uint32_t b2A0 =
        sb + ABYTES + (warpN * WN + 32 + (l15 & 7)) * ROWB + (l15 >> 3) * 16;

    float acc[4][NI][4];
#pragma unroll
    for (int mi = 0; mi < 4; mi++)
#pragma unroll
        for (int ni = 0; ni < NI; ni++)
#pragma unroll
            for (int cc = 0; cc < 4; cc++) acc[mi][ni][cc] = 0.f;

    const int nch = K / 32;

    // prologue: stage chunks 0..3
#pragma unroll
    for (int s = 0; s < 4; s++) {
        const uint32_t ad = adst0 + s * STAGEB;
        const __half* ag = ap + s * 32;
        CP16(ad, ag); CP16(ad + 16, ag + 8);
        if (doB) {
            const uint32_t bd = bdst0 + s * STAGEB;
            const __half* bg = bp + s * 32;
            CP16(bd, bg); CP16(bd + 16, bg + 8);
            CP16(bd + 32, bg + 16); CP16(bd + 48, bg + 24);
        }
        CPCOMMIT();
    }

    uint32_t aF[2][4][4], bq[2][2 * NI];

    CPWAIT(3);
    __syncthreads();
    // preload set 0: (chunk 0, ks 0)
#pragma unroll
    for (int mi = 0; mi < 4; mi++)
        LDSM4(aF[0][mi][0], aF[0][mi][1], aF[0][mi][2], aF[0][mi][3],
              aA0 + mi * (16 * ROWB));
    if (MODE == 0) {
        LDSM4(bq[0][0], bq[0][1], bq[0][2], bq[0][3], bA0);
        LDSM4(bq[0][4], bq[0][5], bq[0][6], bq[0][7], bA0 + 16 * ROWB);
        LDSM4(bq[0][8], bq[0][9], bq[0][10], bq[0][11], bA0 + 32 * ROWB);
    } else {
        LDSM4(bq[0][0], bq[0][1], bq[0][2], bq[0][3], bA0);
        LDSM4(bq[0][4], bq[0][5], bq[0][6], bq[0][7], bA0 + 16 * ROWB);
        LDSM2(bq[0][8], bq[0][9], b2A0);
    }

    int slot = 0, pslot = 4;
    for (int ci = 0; ci < nch; ci++) {
        if (ci + 4 < nch) {
            const uint32_t ad = adst0 + pslot * STAGEB;
            const __half* ag = ap + (ci + 4) * 32;
            CP16(ad, ag); CP16(ad + 16, ag + 8);
            if (doB) {
                const uint32_t bd = bdst0 + pslot * STAGEB;
                const __half* bg = bp + (ci + 4) * 32;
                CP16(bd, bg); CP16(bd + 16, bg + 8);
                CP16(bd + 32, bg + 16); CP16(bd + 48, bg + 24);
            }
            CPCOMMIT();
            pslot = (pslot + 1 == NSTAGE) ? 0 : pslot + 1;
        }
        const uint32_t ab = aA0 + slot * STAGEB;
        const uint32_t bb = bA0 + slot * STAGEB;
        const uint32_t bb2 = b2A0 + slot * STAGEB;
        // load set 1 = (ci, ks1)
#pragma unroll
        for (int mi = 0; mi < 4; mi++)
            LDSM4(aF[1][mi][0], aF[1][mi][1], aF[1][mi][2], aF[1][mi][3],
                  ab + mi * (16 * ROWB) + 32);
        if (MODE == 0) {
            LDSM4(bq[1][0], bq[1][1], bq[1][2], bq[1][3], bb + 32);
            LDSM4(bq[1][4], bq[1][5], bq[1][6], bq[1][7], bb + 16 * ROWB + 32);
            LDSM4(bq[1][8], bq[1][9], bq[1][10], bq[1][11], bb + 32 * ROWB + 32);
        } else {
            LDSM4(bq[1][0], bq[1][1], bq[1][2], bq[1][3], bb + 32);
            LDSM4(bq[1][4], bq[1][5], bq[1][6], bq[1][7], bb + 16 * ROWB + 32);
            LDSM2(bq[1][8], bq[1][9], bb2 + 32);
        }
        // compute ks0 with set 0
#pragma unroll
        for (int mi = 0; mi < 4; mi++)
#pragma unroll
            for (int ni = 0; ni < NI; ni++)
                HMMA(acc[mi][ni], aF[0][mi], bq[0][2 * ni], bq[0][2 * ni + 1]);
        // wait chunk ci+1, sync, load set 0 = (ci+1, ks0)
        if (ci + 1 < nch) {
            const int last = (ci + 4 < nch) ? (ci + 4) : (nch - 1);
            const int ahead = last - (ci + 1);
            if (ahead >= 3) { CPWAIT(3); }
            else if (ahead == 2) { CPWAIT(2); }
            else if (ahead == 1) { CPWAIT(1); }
            else { CPWAIT(0); }
            __syncthreads();
            const int slotn = (slot + 1 == NSTAGE) ? 0 : slot + 1;
            const uint32_t ab2 = aA0 + slotn * STAGEB;
            const uint32_t bbn = bA0 + slotn * STAGEB;
#pragma unroll
            for (int mi = 0; mi < 4; mi++)
                LDSM4(aF[0][mi][0], aF[0][mi][1], aF[0][mi][2], aF[0][mi][3],
                      ab2 + mi * (16 * ROWB));
            if (MODE == 0) {
                LDSM4(bq[0][0], bq[0][1], bq[0][2], bq[0][3], bbn);
                LDSM4(bq[0][4], bq[0][5], bq[0][6], bq[0][7], bbn + 16 * ROWB);
                LDSM4(bq[0][8], bq[0][9], bq[0][10], bq[0][11], bbn + 32 * ROWB);
            } else {
                LDSM4(bq[0][0], bq[0][1], bq[0][2], bq[0][3], bbn);
                LDSM4(bq[0][4], bq[0][5], bq[0][6], bq[0][7], bbn + 16 * ROWB);
                LDSM2(bq[0][8], bq[0][9], b2A0 + slotn * STAGEB);
            }
            slot = slotn;
        }
        // compute ks1 with set 1
#pragma unroll
        for (int mi = 0; mi < 4; mi++)
#pragma unroll
            for (int ni = 0; ni < NI; ni++)
                HMMA(acc[mi][ni], aF[1][mi], bq[1][2 * ni], bq[1][2 * ni + 1]);
    }

    // ================= fused node epilogue (fast math) =================
    const int g = lane >> 2, tt = lane & 3;
    if (MODE == 0) {
        // warp N=48 = 2 groups of [i,o,u] x 8 units
#pragma unroll
        for (int grp = 0; grp < 2; grp++) {
            const int jb = (blockIdx.y * 8 + warpN * 2 + grp) * 8 + tt * 2;
            const float bi0 = b_iou[jb], bi1 = b_iou[jb + 1];
            const float bo0 = b_iou[256 + jb], bo1 = b_iou[257 + jb];
            const float bu0 = b_iou[512 + jb], bu1 = b_iou[513 + jb];
#pragma unroll
            for (int mi = 0; mi < 4; mi++) {
#pragma unroll
                for (int hf = 0; hf < 2; hf++) {
                    const int r = rowStart + warpM * 64 + mi * 16 + g + hf * 8;
                    const int b = r >> 9, l = r & 511;
                    const size_t idx =
                        ((size_t)(b * Nx + (NLEAF - 1) + l)) * Hx + jb;
                    const float iv0 = acc[mi][grp * 3 + 0][hf * 2 + 0] + bi0;
                    const float iv1 = acc[mi][grp * 3 + 0][hf * 2 + 1] + bi1;
                    const float ov0 = acc[mi][grp * 3 + 1][hf * 2 + 0] + bo0;
                    const float ov1 = acc[mi][grp * 3 + 1][hf * 2 + 1] + bo1;
                    const float uv0 = acc[mi][grp * 3 + 2][hf * 2 + 0] + bu0;
                    const float uv1 = acc[mi][grp * 3 + 2][hf * 2 + 1] + bu1;
                    const float2 cz = *(const float2*)(c0 + idx);
                    const float cA = sigm(iv0) * ftanh(uv0) + cz.x;
                    const float cB = sigm(iv1) * ftanh(uv1) + cz.y;
                    const float hA = sigm(ov0) * ftanh(cA);
                    const float hB = sigm(ov1) * ftanh(cB);
                    *(float2*)(g_c + idx) = make_float2(cA, cB);
                    *(float2*)(g_h + idx) = make_float2(hA, hB);
                    *(__half2*)(g_h16 + idx) = __floats2half2_rn(hA, hB);
                }
            }
        }
    } else {
        // warp N=40 = 1 group of [f1,f2,i,o,u] x 8 units
        const int jb = (blockIdx.y * 4 + warpN) * 8 + tt * 2;
        const float bf10 = Uf_b[jb], bf11 = Uf_b[jb + 1];
        const float bf20 = Uf_b[256 + jb], bf21 = Uf_b[257 + jb];
        const float bi0 = b_iou[jb], bi1 = b_iou[jb + 1];
        const float bo0 = b_iou[256 + jb], bo1 = b_iou[257 + jb];
        const float bu0 = b_iou[512 + jb], bu1 = b_iou[513 + jb];
        const int mask = (1 << shift) - 1;
#pragma unroll
        for (int mi = 0; mi < 4; mi++) {
#pragma unroll
            for (int hf = 0; hf < 2; hf++) {
                const int r = rowStart + warpM * 64 + mi * 16 + g + hf * 8;
                const int b = r >> shift, pl = r & mask;
                const int p = ps + pl;
                const size_t cidx = ((size_t)(b * Nx + 2 * p + 1)) * Hx + jb;
                const float2 c1 = *(const float2*)(g_c + cidx);
                const float2 c2 = *(const float2*)(g_c + cidx + Hx);
                const float f10 = sigm(acc[mi][0][hf * 2 + 0] + bf10);
                const float f11 = sigm(acc[mi][0][hf * 2 + 1] + bf11);
                const float f20 = sigm(acc[mi][1][hf * 2 + 0] + bf20);
                const float f21 = sigm(acc[mi][1][hf * 2 + 1] + bf21);
                const float cs0 = f10 * c1.x + f20 * c2.x;
                const float cs1 = f11 * c1.y + f21 * c2.y;
                const float iv0 = acc[mi][2][hf * 2 + 0] + bi0;
                const float iv1 = acc[mi][2][hf * 2 + 1] + bi1;
                const float ov0 = acc[mi][3][hf * 2 + 0] + bo0;
                const float ov1 = acc[mi][3][hf * 2 + 1] + bo1;
                const float uv0 = acc[mi][4][hf * 2 + 0] + bu0;
                const float uv1 = acc[mi][4][hf * 2 + 1] + bu1;
                const float cA = sigm(iv0) * ftanh(uv0) + cs0;
                const float cB = sigm(iv1) * ftanh(uv1) + cs1;
                const float hA = sigm(ov0) * ftanh(cA);
                const float hB = sigm(ov1) * ftanh(cB);
                const size_t pidx = ((size_t)(b * Nx + p)) * Hx + jb;
                *(float2*)(g_c + pidx) = make_float2(cA, cB);
                *(float2*)(g_h + pidx) = make_float2(hA, hB);
                *(__half2*)(g_h16 + pidx) = __floats2half2_rn(hA, hB);
            }
        }
    }
}

// ---- q[b] = Wmem^T @ h[b,0,:]  (scores factored: dec^T Wmem h = q . h) ----
__global__ void q_k(const float* __restrict__ Wmem) {
    int b = blockIdx.x, h = threadIdx.x;
    __shared__ float dec[256];
    dec[h] = g_h[((size_t)(b * Nx)) * Hx + h];
    __syncthreads();
    float s = 0.f;
#pragma unroll 4
    for (int g = 0; g < 256; g++) s += dec[g] * Wmem[g * 256 + h];
    g_q[b * Hx + h] = s;
}

// ---- per-batch fused scores + softmax + context ----
__global__ __launch_bounds__(1024) void attn_k() {
    __shared__ float q[256];
    __shared__ float sc[1024];
    __shared__ float red[32];
    __shared__ float ctxp[4][256];
    __shared__ float stat[2];
    int b = blockIdx.x, tid = threadIdx.x;
    int warp = tid >> 5, lane = tid & 31;
    if (tid < 256) q[tid] = g_q[b * Hx + tid];
    __syncthreads();
    const float* hb = g_h + (size_t)b * Nx * Hx;
    for (int n = warp; n < Nx; n += 32) {
        const float* hr = hb + (size_t)n * Hx;
        float s = 0.f;
#pragma unroll
        for (int kk = 0; kk < 8; kk++) s += q[lane + kk * 32] * hr[lane + kk * 32];
#pragma unroll
        for (int o = 16; o; o >>= 1) s += __shfl_xor_sync(0xffffffffu, s, o);
        if (lane == 0) sc[n] = s;
    }
    __syncthreads();
    float sraw = (tid < Nx) ? sc[tid] : -3.4e38f;
    float v = sraw;
#pragma unroll
    for (int o = 16; o; o >>= 1) v = fmaxf(v, __shfl_xor_sync(0xffffffffu, v, o));
    if (lane == 0) red[warp] = v;
    __syncthreads();
    if (warp == 0) {
        float m = red[lane];
#pragma unroll
        for (int o = 16; o; o >>= 1) m = fmaxf(m, __shfl_xor_sync(0xffffffffu, m, o));
        if (lane == 0) stat[0] = m;
    }
    __syncthreads();
    float m = stat[0];
    float e = (tid < Nx) ? __expf(sraw - m) : 0.f;
    sc[tid] = e;
    float s = e;
#pragma unroll
    for (int o = 16; o; o >>= 1) s += __shfl_xor_sync(0xffffffffu, s, o);
    if (lane == 0) red[warp] = s;
    __syncthreads();
    if (warp == 0) {
        float S = red[lane];
#pragma unroll
        for (int o = 16; o; o >>= 1) S += __shfl_xor_sync(0xffffffffu, S, o);
        if (lane == 0) stat[1] = S;
    }
    __syncthreads();
    float Sinv = __fdividef(1.f, stat[1]);
    int grp = tid >> 8, j = tid & 255;
    float p = 0.f;
    for (int n = grp; n < Nx; n += 4) p += sc[n] * hb[(size_t)n * Hx + j];
    ctxp[grp][j] = p;
    __syncthreads();
    if (tid < 256) {
        g_ctx[b * Hx + tid] =
            (ctxp[0][tid] + ctxp[1][tid] + ctxp[2][tid] + ctxp[3][tid]) * Sinv;
    }
}

// ---- head: hid = relu(ctx @ wh_W^T + wh_b); out = hid @ lin_W^T + lin_b ----
__global__ void final_k(const float* __restrict__ wh_W,
                        const float* __restrict__ wh_b,
                        const float* __restrict__ lin_W,
                        const float* __restrict__ lin_b,
                        float* __restrict__ out) {
    int b = blockIdx.x, tid = threadIdx.x;
    int warp = tid >> 5, lane = tid & 31;
    __shared__ float ctx[256];
    __shared__ float hid[256];
    ctx[tid] = g_ctx[b * Hx + tid];
    __syncthreads();
    for (int h = warp; h < 256; h += 8) {
        const float* wr = wh_W + (size_t)h * 256;
        float s = 0.f;
#pragma unroll
        for (int kk = 0; kk < 8; kk++) s += ctx[lane + kk * 32] * wr[lane + kk * 32];
#pragma unroll
        for (int o = 16; o; o >>= 1) s += __shfl_xor_sync(0xffffffffu, s, o);
        if (lane == 0) hid[h] = fmaxf(s + wh_b[h], 0.f);
    }
    __syncthreads();
    if (warp == 0) {
        for (int cc = 0; cc < Cx; cc++) {
            const float* lr = lin_W + (size_t)cc * 256;
            float s = 0.f;
#pragma unroll
            for (int kk = 0; kk < 8; kk++) s += hid[lane + kk * 32] * lr[lane + kk * 32];
#pragma unroll
            for (int o = 16; o; o >>= 1) s += __shfl_xor_sync(0xffffffffu, s, o);
            if (lane == 0) out[b * Cx + cc] = s + lin_b[cc];
        }
    }
}

extern "C" void kernel_launch(void* const* d_in, const int* in_sizes, int n_in,
                              void* d_out, int out_size) {
    const int* wordid   = (const int*)d_in[0];
    // d_in[1] = h0 (unused: every node is overwritten)
    const float* c0     = (const float*)d_in[2];
    const float* emb    = (const float*)d_in[3];
    const float* W_iou  = (const float*)d_in[4];
    const float* U_iou  = (const float*)d_in[5];
    const float* b_iou  = (const float*)d_in[6];
    const float* Uf_W   = (const float*)d_in[7];
    const float* Uf_b   = (const float*)d_in[8];
    const float* Wmem   = (const float*)d_in[9];
    const float* wh_W   = (const float*)d_in[10];
    const float* wh_b   = (const float*)d_in[11];
    const float* lin_W  = (const float*)d_in[12];
    const float* lin_b  = (const float*)d_in[13];
    float* out = (float*)d_out;
    (void)in_sizes; (void)n_in; (void)out_size;

    const int SMEM0 = NSTAGE * (128 + 192) * ROWB;   // 128000
    const int SMEM1 = NSTAGE * (128 + 160) * ROWB;   // 115200
    cudaFuncSetAttribute(hgemm_k<0>, cudaFuncAttributeMaxDynamicSharedMemorySize,
                         SMEM0);
    cudaFuncSetAttribute(hgemm_k<1>, cudaFuncAttributeMaxDynamicSharedMemorySize,
                         SMEM1);

    // fp16 mirrors (gate-interleaved weights)
    emb16_k<<<(Vx * Xx + 255) / 256, 256>>>(emb);
    wiou16_k<<<(GH3 * Xx + 255) / 256, 256>>>(W_iou);
    wc16_k<<<(NC * K2H + 255) / 256, 256>>>(Uf_W, U_iou);

    // Leaves fused: GEMM + node -> h/c at nodes 511..1022
    hgemm_k<0><<<dim3(Bx * NLEAF / 128, GH3 / 192), 256, SMEM0>>>(
        wordid, c0, b_iou, Uf_b, Xx, 0, 0);

    // Tree levels (serial), fused GEMM + node per level
    for (int level = 8; level >= 0; level--) {
        int npar = 1 << level, ps = npar - 1;
        hgemm_k<1><<<dim3(npar, NC / 160), 256, SMEM1>>>(
            nullptr, nullptr, b_iou, Uf_b, K2H, ps, level);
    }

    // Attention + head
    q_k<<<Bx, 256>>>(Wmem);
    attn_k<<<Bx, 1024>>>();
    final_k<<<Bx, 256>>>(wh_W, wh_b, lin_W, lin_b, out);
}

// round 11
// speedup vs baseline: 3.6467x; 1.0407x over previous
#include <cuda_runtime.h>
#include <cuda_fp16.h>
#include <math.h>
#include <stdint.h>

#define Bx 128
#define Nx 1023
#define Hx 256
#define Xx 256
#define Cx 10
#define Vx 32000
#define NLEAF 512
#define GH3 768      // 3*H
#define NC 1280      // 2H (f gates) + 3H (iou)
#define K2H 512      // 2*H

// ---- device-global scratch (no allocations allowed) ----
__device__ __half g_h16[(size_t)Bx * Nx * Hx];        // fp16 h (GEMM A + attention)
__device__ float g_c[(size_t)Bx * Nx * Hx];           // fp32 c
__device__ __half g_emb16[(size_t)Vx * Xx];
__device__ __half g_Wc16[NC * K2H];     // gate-interleaved [f1,f2,i,o,u]x8 groups
__device__ __half g_Wiou16[GH3 * Xx];   // gate-interleaved [i,o,u]x8 groups
__device__ float g_q[Bx * Hx];
__device__ float g_ctx[Bx * Hx];

// fast transcendentals: MUFU-based, rel err ~1e-6
__device__ __forceinline__ float sigm(float x) {
    return __fdividef(1.f, 1.f + __expf(-x));
}
__device__ __forceinline__ float ftanh(float x) {
    x = fminf(fmaxf(x, -15.f), 15.f);     // avoid inf/inf; tanh(15)==1 in fp32
    float e = __expf(2.f * x);
    return __fdividef(e - 1.f, e + 1.f);
}

#define LDSM4(r0, r1, r2, r3, addr)                                          \
    asm volatile("ldmatrix.sync.aligned.m8n8.x4.shared.b16 {%0,%1,%2,%3}, [%4];" \
                 : "=r"(r0), "=r"(r1), "=r"(r2), "=r"(r3) : "r"(addr))
#define LDSM2(r0, r1, addr)                                                  \
    asm volatile("ldmatrix.sync.aligned.m8n8.x2.shared.b16 {%0,%1}, [%2];"   \
                 : "=r"(r0), "=r"(r1) : "r"(addr))

#define HMMA(d, a, b0, b1)                                                   \
    asm volatile(                                                            \
        "mma.sync.aligned.m16n8k16.row.col.f32.f16.f16.f32 "                 \
        "{%0,%1,%2,%3}, {%4,%5,%6,%7}, {%8,%9}, {%0,%1,%2,%3};"              \
        : "+f"(d[0]), "+f"(d[1]), "+f"(d[2]), "+f"(d[3])                     \
        : "r"(a[0]), "r"(a[1]), "r"(a[2]), "r"(a[3]), "r"(b0), "r"(b1))

#define CP16(dst, src)                                                       \
    asm volatile("cp.async.cg.shared.global [%0], [%1], 16;" ::"r"(dst),     \
                 "l"(src))
#define CPCOMMIT() asm volatile("cp.async.commit_group;")
#define CPWAIT(n) asm volatile("cp.async.wait_group %0;" ::"n"(n))

__device__ __forceinline__ uint32_t smem_u32(const void* p) {
    uint32_t a;
    asm("{ .reg .u64 t; cvta.to.shared.u64 t, %1; cvt.u32.u64 %0, t; }"
        : "=r"(a) : "l"(p));
    return a;
}

// ---- fp16 mirror setup (with gate interleave) ----
__global__ void emb16_k(const float* __restrict__ emb) {
    int i = blockIdx.x * 256 + threadIdx.x;
    if (i < Vx * Xx) g_emb16[i] = __float2half(emb[i]);
}
__global__ void wiou16_k(const float* __restrict__ W_iou) {
    int i = blockIdx.x * 256 + threadIdx.x;
    if (i >= GH3 * Xx) return;
    int r = i >> 8, k = i & 255;
    int w = r % 24, gate = w >> 3, j = (r / 24) * 8 + (w & 7);
    g_Wiou16[i] = __float2half(W_iou[(gate * 256 + j) * Xx + k]);
}
__global__ void wc16_k(const float* __restrict__ Uf_W,
                       const float* __restrict__ U_iou) {
    int i = blockIdx.x * 256 + threadIdx.x;
    if (i >= NC * K2H) return;
    int r = i >> 9, k = i & 511;
    int w = r % 40, gate = w >> 3, j = (r / 40) * 8 + (w & 7);
    float v = (gate < 2) ? Uf_W[(gate * 256 + j) * K2H + k]
                         : U_iou[((gate - 2) * 256 + j) * K2H + k];
    g_Wc16[i] = __float2half(v);
}

// ===================================================================
// Fused FP16 tensor GEMM + TreeLSTM node epilogue.
// K-chunk 64 (half the barriers of R10), 4-stage cp.async ring:
//   wait(<=2) -> __syncthreads -> commit chunk ci+3 -> compute 4 ks.
// Row pad 72 halves (144B): stride 36 words == 4 mod 32 -> ldmatrix
// phases conflict-free.
// MODE 0 (leaf):  NBLK=192, warp N=48 = 2 groups of [i,o,u]x8. K=256.
// MODE 1 (level): NBLK=160, warp N=40 = 1 group of [f1,f2,i,o,u]x8. K=512.
// ===================================================================
#define ROWB 144
#define ABYTES (128 * ROWB)
#define NSTAGE 4

template <int MODE>
__global__ __launch_bounds__(256, 1) void hgemm_k(
    const int* __restrict__ wordid, const float* __restrict__ c0,
    const float* __restrict__ b_iou, const float* __restrict__ Uf_b,
    int K, int ps, int shift) {
    constexpr int NBLK = MODE ? 160 : 192;
    constexpr int NI = MODE ? 5 : 6;       // n8 tiles per warp
    constexpr int WN = MODE ? 40 : 48;     // warp N width
    constexpr int STAGEB = (128 + NBLK) * ROWB;
    extern __shared__ char smem[];
    const uint32_t sb = smem_u32(smem);
    const int tid = threadIdx.x, lane = tid & 31, warp = tid >> 5;
    const int rowStart = blockIdx.x * 128, colStart = blockIdx.y * NBLK;
    const int warpM = warp >> 2, warpN = warp & 3;

    // --- staging pointers: A row tid>>1 (32-half slice), B row tid ---
    const int sr = tid >> 1;
    const __half* ap;
    {
        int r = rowStart + sr;
        if (MODE == 0) {
            int b = r >> 9, l = r & 511;
            int w = wordid[b * Nx + (NLEAF - 1) + l];
            ap = g_emb16 + (size_t)w * Xx + (tid & 1) * 32;
        } else {
            int b = r >> shift, pl = r & ((1 << shift) - 1);
            ap = g_h16 + ((size_t)(b * Nx + 2 * (ps + pl) + 1)) * Hx +
                 (tid & 1) * 32;
        }
    }
    const int bcol = colStart + (tid < NBLK ? tid : 0);
    const __half* bp =
        (MODE == 0 ? (const __half*)g_Wiou16 : (const __half*)g_Wc16) +
        (size_t)bcol * K;
    const uint32_t adst0 = sb + sr * ROWB + (tid & 1) * 64;
    const uint32_t bdst0 = sb + ABYTES + (tid < NBLK ? tid : 0) * ROWB;
    const bool doB = (tid < NBLK);

    // --- ldmatrix bases ---
    const int aRow = warpM * 64 + (lane & 7) + ((lane >> 3) & 1) * 8;
    const int aK = (lane >> 4) * 8;
    const int bRow = warpN * WN + (lane & 7) + ((lane >> 4) & 1) * 8;
    const int bK = ((lane >> 3) & 1) * 8;
    const uint32_t aA0 = sb + aRow * ROWB + aK * 2;
    const uint32_t bA0 = sb + ABYTES + bRow * ROWB + bK * 2;
    const int l15 = lane & 15;
    const uint32_t b2A0 =
        sb + ABYTES + (warpN * WN + 32 + (l15 & 7)) * ROWB + (l15 >> 3) * 16;

    float acc[4][NI][4];
#pragma unroll
    for (int mi = 0; mi < 4; mi++)
#pragma unroll
        for (int ni = 0; ni < NI; ni++)
#pragma unroll
            for (int cc = 0; cc < 4; cc++) acc[mi][ni][cc] = 0.f;

    const int nch = K / 64;   // leaf: 4, level: 8

    // prologue: stage chunks 0..2 into slots 0..2
#pragma unroll
    for (int s = 0; s < 3; s++) {
        const uint32_t ad = adst0 + s * STAGEB;
        const __half* ag = ap + s * 64;
        CP16(ad, ag); CP16(ad + 16, ag + 8);
        CP16(ad + 32, ag + 16); CP16(ad + 48, ag + 24);
        if (doB) {
            const uint32_t bd = bdst0 + s * STAGEB;
            const __half* bg = bp + s * 64;
            CP16(bd, bg); CP16(bd + 16, bg + 8);
            CP16(bd + 32, bg + 16); CP16(bd + 48, bg + 24);
            CP16(bd + 64, bg + 32); CP16(bd + 80, bg + 40);
            CP16(bd + 96, bg + 48); CP16(bd + 112, bg + 56);
        }
        CPCOMMIT();
    }

    for (int ci = 0; ci < nch; ci++) {
        const int rem = nch - 1 - ci;
        if (rem >= 2) { CPWAIT(2); }
        else if (rem == 1) { CPWAIT(1); }
        else { CPWAIT(0); }
        __syncthreads();
        if (ci + 3 < nch) {
            const int s = (ci + 3) & 3;
            const uint32_t ad = adst0 + s * STAGEB;
            const __half* ag = ap + (ci + 3) * 64;
            CP16(ad, ag); CP16(ad + 16, ag + 8);
            CP16(ad + 32, ag + 16); CP16(ad + 48, ag + 24);
            if (doB) {
                const uint32_t bd = bdst0 + s * STAGEB;
                const __half* bg = bp + (ci + 3) * 64;
                CP16(bd, bg); CP16(bd + 16, bg + 8);
                CP16(bd + 32, bg + 16); CP16(bd + 48, bg + 24);
                CP16(bd + 64, bg + 32); CP16(bd + 80, bg + 40);
                CP16(bd + 96, bg + 48); CP16(bd + 112, bg + 56);
            }
            CPCOMMIT();
        }
        const int slot = ci & 3;
        const uint32_t ab = aA0 + slot * STAGEB;
        const uint32_t bb = bA0 + slot * STAGEB;
        const uint32_t bb2 = b2A0 + slot * STAGEB;
#pragma unroll
        for (int ks = 0; ks < 4; ks++) {
            uint32_t aF[4][4], bq[2 * NI];
#pragma unroll
            for (int mi = 0; mi < 4; mi++)
                LDSM4(aF[mi][0], aF[mi][1], aF[mi][2], aF[mi][3],
                      ab + mi * (16 * ROWB) + ks * 32);
            if (MODE == 0) {
                LDSM4(bq[0], bq[1], bq[2], bq[3], bb + ks * 32);
                LDSM4(bq[4], bq[5], bq[6], bq[7], bb + 16 * ROWB + ks * 32);
                LDSM4(bq[8], bq[9], bq[10], bq[11], bb + 32 * ROWB + ks * 32);
            } else {
                LDSM4(bq[0], bq[1], bq[2], bq[3], bb + ks * 32);
                LDSM4(bq[4], bq[5], bq[6], bq[7], bb + 16 * ROWB + ks * 32);
                LDSM2(bq[8], bq[9], bb2 + ks * 32);
            }
#pragma unroll
            for (int mi = 0; mi < 4; mi++)
#pragma unroll
                for (int ni = 0; ni < NI; ni++)
                    HMMA(acc[mi][ni], aF[mi], bq[2 * ni], bq[2 * ni + 1]);
        }
    }

    // ================= fused node epilogue (fast math) =================
    const int g = lane >> 2, tt = lane & 3;
    if (MODE == 0) {
        // warp N=48 = 2 groups of [i,o,u] x 8 units
#pragma unroll
        for (int grp = 0; grp < 2; grp++) {
            const int jb = (blockIdx.y * 8 + warpN * 2 + grp) * 8 + tt * 2;
            const float bi0 = b_iou[jb], bi1 = b_iou[jb + 1];
            const float bo0 = b_iou[256 + jb], bo1 = b_iou[257 + jb];
            const float bu0 = b_iou[512 + jb], bu1 = b_iou[513 + jb];
#pragma unroll
            for (int mi = 0; mi < 4; mi++) {
#pragma unroll
                for (int hf = 0; hf < 2; hf++) {
                    const int r = rowStart + warpM * 64 + mi * 16 + g + hf * 8;
                    const int b = r >> 9, l = r & 511;
                    const size_t idx =
                        ((size_t)(b * Nx + (NLEAF - 1) + l)) * Hx + jb;
                    const float iv0 = acc[mi][grp * 3 + 0][hf * 2 + 0] + bi0;
                    const float iv1 = acc[mi][grp * 3 + 0][hf * 2 + 1] + bi1;
                    const float ov0 = acc[mi][grp * 3 + 1][hf * 2 + 0] + bo0;
                    const float ov1 = acc[mi][grp * 3 + 1][hf * 2 + 1] + bo1;
                    const float uv0 = acc[mi][grp * 3 + 2][hf * 2 + 0] + bu0;
                    const float uv1 = acc[mi][grp * 3 + 2][hf * 2 + 1] + bu1;
                    const float2 cz = *(const float2*)(c0 + idx);
                    const float cA = sigm(iv0) * ftanh(uv0) + cz.x;
                    const float cB = sigm(iv1) * ftanh(uv1) + cz.y;
                    const float hA = sigm(ov0) * ftanh(cA);
                    const float hB = sigm(ov1) * ftanh(cB);
                    *(float2*)(g_c + idx) = make_float2(cA, cB);
                    *(__half2*)(g_h16 + idx) = __floats2half2_rn(hA, hB);
                }
            }
        }
    } else {
        // warp N=40 = 1 group of [f1,f2,i,o,u] x 8 units
        const int jb = (blockIdx.y * 4 + warpN) * 8 + tt * 2;
        const float bf10 = Uf_b[jb], bf11 = Uf_b[jb + 1];
        const float bf20 = Uf_b[256 + jb], bf21 = Uf_b[257 + jb];
        const float bi0 = b_iou[jb], bi1 = b_iou[jb + 1];
        const float bo0 = b_iou[256 + jb], bo1 = b_iou[257 + jb];
        const float bu0 = b_iou[512 + jb], bu1 = b_iou[513 + jb];
        const int mask = (1 << shift) - 1;
#pragma unroll
        for (int mi = 0; mi < 4; mi++) {
#pragma unroll
            for (int hf = 0; hf < 2; hf++) {
                const int r = rowStart + warpM * 64 + mi * 16 + g + hf * 8;
                const int b = r >> shift, pl = r & mask;
                const int p = ps + pl;
                const size_t cidx = ((size_t)(b * Nx + 2 * p + 1)) * Hx + jb;
                const float2 c1 = *(const float2*)(g_c + cidx);
                const float2 c2 = *(const float2*)(g_c + cidx + Hx);
                const float f10 = sigm(acc[mi][0][hf * 2 + 0] + bf10);
                const float f11 = sigm(acc[mi][0][hf * 2 + 1] + bf11);
                const float f20 = sigm(acc[mi][1][hf * 2 + 0] + bf20);
                const float f21 = sigm(acc[mi][1][hf * 2 + 1] + bf21);
                const float cs0 = f10 * c1.x + f20 * c2.x;
                const float cs1 = f11 * c1.y + f21 * c2.y;
                const float iv0 = acc[mi][2][hf * 2 + 0] + bi0;
                const float iv1 = acc[mi][2][hf * 2 + 1] + bi1;
                const float ov0 = acc[mi][3][hf * 2 + 0] + bo0;
                const float ov1 = acc[mi][3][hf * 2 + 1] + bo1;
                const float uv0 = acc[mi][4][hf * 2 + 0] + bu0;
                const float uv1 = acc[mi][4][hf * 2 + 1] + bu1;
                const float cA = sigm(iv0) * ftanh(uv0) + cs0;
                const float cB = sigm(iv1) * ftanh(uv1) + cs1;
                const float hA = sigm(ov0) * ftanh(cA);
                const float hB = sigm(ov1) * ftanh(cB);
                const size_t pidx = ((size_t)(b * Nx + p)) * Hx + jb;
                *(float2*)(g_c + pidx) = make_float2(cA, cB);
                *(__half2*)(g_h16 + pidx) = __floats2half2_rn(hA, hB);
            }
        }
    }
}

// ---- q[b] = Wmem^T @ h16[b,0,:]  (scores factored: dec^T Wmem h = q . h) ----
__global__ void q_k(const float* __restrict__ Wmem) {
    int b = blockIdx.x, h = threadIdx.x;
    __shared__ float dec[256];
    dec[h] = __half2float(g_h16[((size_t)(b * Nx)) * Hx + h]);
    __syncthreads();
    float s = 0.f;
#pragma unroll 4
    for (int g = 0; g < 256; g++) s += dec[g] * Wmem[g * 256 + h];
    g_q[b * Hx + h] = s;
}

// ---- per-batch fused scores + softmax + context (h from g_h16) ----
__global__ __launch_bounds__(1024) void attn_k() {
    __shared__ float q[256];
    __shared__ float sc[1024];
    __shared__ float red[32];
    __shared__ float ctxp[4][256];
    __shared__ float stat[2];
    int b = blockIdx.x, tid = threadIdx.x;
    int warp = tid >> 5, lane = tid & 31;
    if (tid < 256) q[tid] = g_q[b * Hx + tid];
    __syncthreads();
    const __half* hb = g_h16 + (size_t)b * Nx * Hx;
    for (int n = warp; n < Nx; n += 32) {
        const __half2* hr2 = (const __half2*)(hb + (size_t)n * Hx);
        float s = 0.f;
#pragma unroll
        for (int kk = 0; kk < 4; kk++) {
            int i2 = lane + kk * 32;
            float2 f = __half22float2(hr2[i2]);
            s += q[2 * i2] * f.x + q[2 * i2 + 1] * f.y;
        }
#pragma unroll
        for (int o = 16; o; o >>= 1) s += __shfl_xor_sync(0xffffffffu, s, o);
        if (lane == 0) sc[n] = s;
    }
    __syncthreads();
    float sraw = (tid < Nx) ? sc[tid] : -3.4e38f;
    float v = sraw;
#pragma unroll
    for (int o = 16; o; o >>= 1) v = fmaxf(v, __shfl_xor_sync(0xffffffffu, v, o));
    if (lane == 0) red[warp] = v;
    __syncthreads();
    if (warp == 0) {
        float m = red[lane];
#pragma unroll
        for (int o = 16; o; o >>= 1) m = fmaxf(m, __shfl_xor_sync(0xffffffffu, m, o));
        if (lane == 0) stat[0] = m;
    }
    __syncthreads();
    float m = stat[0];
    float e = (tid < Nx) ? __expf(sraw - m) : 0.f;
    sc[tid] = e;
    float s = e;
#pragma unroll
    for (int o = 16; o; o >>= 1) s += __shfl_xor_sync(0xffffffffu, s, o);
    if (lane == 0) red[warp] = s;
    __syncthreads();
    if (warp == 0) {
        float S = red[lane];
#pragma unroll
        for (int o = 16; o; o >>= 1) S += __shfl_xor_sync(0xffffffffu, S, o);
        if (lane == 0) stat[1] = S;
    }
    __syncthreads();
    float Sinv = __fdividef(1.f, stat[1]);
    int grp = tid >> 8, j = tid & 255;
    float p = 0.f;
    for (int n = grp; n < Nx; n += 4)
        p += sc[n] * __half2float(hb[(size_t)n * Hx + j]);
    ctxp[grp][j] = p;
    __syncthreads();
    if (tid < 256) {
        g_ctx[b * Hx + tid] =
            (ctxp[0][tid] + ctxp[1][tid] + ctxp[2][tid] + ctxp[3][tid]) * Sinv;
    }
}

// ---- head: hid = relu(ctx @ wh_W^T + wh_b); out = hid @ lin_W^T + lin_b ----
__global__ void final_k(const float* __restrict__ wh_W,
                        const float* __restrict__ wh_b,
                        const float* __restrict__ lin_W,
                        const float* __restrict__ lin_b,
                        float* __restrict__ out) {
    int b = blockIdx.x, tid = threadIdx.x;
    int warp = tid >> 5, lane = tid & 31;
    __shared__ float ctx[256];
    __shared__ float hid[256];
    ctx[tid] = g_ctx[b * Hx + tid];
    __syncthreads();
    for (int h = warp; h < 256; h += 8) {
        const float* wr = wh_W + (size_t)h * 256;
        float s = 0.f;
#pragma unroll
        for (int kk = 0; kk < 8; kk++) s += ctx[lane + kk * 32] * wr[lane + kk * 32];
#pragma unroll
        for (int o = 16; o; o >>= 1) s += __shfl_xor_sync(0xffffffffu, s, o);
        if (lane == 0) hid[h] = fmaxf(s + wh_b[h], 0.f);
    }
    __syncthreads();
    if (warp == 0) {
        for (int cc = 0; cc < Cx; cc++) {
            const float* lr = lin_W + (size_t)cc * 256;
            float s = 0.f;
#pragma unroll
            for (int kk = 0; kk < 8; kk++) s += hid[lane + kk * 32] * lr[lane + kk * 32];
#pragma unroll
            for (int o = 16; o; o >>= 1) s += __shfl_xor_sync(0xffffffffu, s, o);
            if (lane == 0) out[b * Cx + cc] = s + lin_b[cc];
        }
    }
}

extern "C" void kernel_launch(void* const* d_in, const int* in_sizes, int n_in,
                              void* d_out, int out_size) {
    const int* wordid   = (const int*)d_in[0];
    // d_in[1] = h0 (unused: every node is overwritten)
    const float* c0     = (const float*)d_in[2];
    const float* emb    = (const float*)d_in[3];
    const float* W_iou  = (const float*)d_in[4];
    const float* U_iou  = (const float*)d_in[5];
    const float* b_iou  = (const float*)d_in[6];
    const float* Uf_W   = (const float*)d_in[7];
    const float* Uf_b   = (const float*)d_in[8];
    const float* Wmem   = (const float*)d_in[9];
    const float* wh_W   = (const float*)d_in[10];
    const float* wh_b   = (const float*)d_in[11];
    const float* lin_W  = (const float*)d_in[12];
    const float* lin_b  = (const float*)d_in[13];
    float* out = (float*)d_out;
    (void)in_sizes; (void)n_in; (void)out_size;

    const int SMEM0 = NSTAGE * (128 + 192) * ROWB;   // 184320
    const int SMEM1 = NSTAGE * (128 + 160) * ROWB;   // 165888
    cudaFuncSetAttribute(hgemm_k<0>, cudaFuncAttributeMaxDynamicSharedMemorySize,
                         SMEM0);
    cudaFuncSetAttribute(hgemm_k<1>, cudaFuncAttributeMaxDynamicSharedMemorySize,
                         SMEM1);

    // fp16 mirrors (gate-interleaved weights)
    emb16_k<<<(Vx * Xx + 255) / 256, 256>>>(emb);
    wiou16_k<<<(GH3 * Xx + 255) / 256, 256>>>(W_iou);
    wc16_k<<<(NC * K2H + 255) / 256, 256>>>(Uf_W, U_iou);

    // Leaves fused: GEMM + node -> h/c at nodes 511..1022
    hgemm_k<0><<<dim3(Bx * NLEAF / 128, GH3 / 192), 256, SMEM0>>>(
        wordid, c0, b_iou, Uf_b, Xx, 0, 0);

    // Tree levels (serial), fused GEMM + node per level
    for (int level = 8; level >= 0; level--) {
        int npar = 1 << level, ps = npar - 1;
        hgemm_k<1><<<dim3(npar, NC / 160), 256, SMEM1>>>(
            nullptr, nullptr, b_iou, Uf_b, K2H, ps, level);
    }

    // Attention + head
    q_k<<<Bx, 256>>>(Wmem);
    attn_k<<<Bx, 1024>>>();
    final_k<<<Bx, 256>>>(wh_W, wh_b, lin_W, lin_b, out);
}